// round 1
// baseline (speedup 1.0000x reference)
#include <cuda_runtime.h>
#include <math.h>

#define NN   50000
#define EE   800000
#define RRR  32
#define DIN  128
#define HHH  8
#define DDD  16
#define HD   128

// ---------------- device scratch (module-load allocated, allowed) ----------------
__device__ float g_fhead[NN * HD];
__device__ float g_ftail[NN * HD];
__device__ float g_fent [NN * HD];
__device__ float g_featA[NN * HD];
__device__ float g_featB[NN * HD];
__device__ float g_attn [EE * HHH];      // scores, then softmaxed attention
__device__ float g_er   [RRR * HHH];
__device__ float g_login[NN];            // log(deg) / sqrt(D)
__device__ int   g_deg   [NN];
__device__ int   g_rowptr[NN + 1];
__device__ int   g_cursor[NN];
__device__ int   g_eperm [EE];

// ---------------- CSR build ----------------
__global__ void k_zero_deg() {
    int i = blockIdx.x * blockDim.x + threadIdx.x;
    if (i < NN) g_deg[i] = 0;
}

__global__ void k_hist(const int* __restrict__ dst) {
    int e = blockIdx.x * blockDim.x + threadIdx.x;
    if (e < EE) atomicAdd(&g_deg[dst[e]], 1);
}

__global__ void k_scan() {   // 1 block, 1024 threads
    __shared__ int sums[1024];
    int tid = threadIdx.x;
    const int C = (NN + 1023) / 1024;
    int start = tid * C;
    int end   = min(start + C, NN);
    int s = 0;
    for (int i = start; i < end; i++) s += g_deg[i];
    sums[tid] = s;
    __syncthreads();
    for (int off = 1; off < 1024; off <<= 1) {
        int v = (tid >= off) ? sums[tid - off] : 0;
        __syncthreads();
        sums[tid] += v;
        __syncthreads();
    }
    int base = (tid == 0) ? 0 : sums[tid - 1];
    for (int i = start; i < end; i++) {
        g_rowptr[i] = base;
        int d = g_deg[i];
        g_login[i] = logf((float)max(d, 1)) * 0.25f;   // /sqrt(16)
        g_cursor[i] = 0;
        base += d;
    }
    if (tid == 1023) g_rowptr[NN] = sums[1023];
}

__global__ void k_scatter(const int* __restrict__ dst) {
    int e = blockIdx.x * blockDim.x + threadIdx.x;
    if (e < EE) {
        int d = dst[e];
        int p = atomicAdd(&g_cursor[d], 1);
        g_eperm[g_rowptr[d] + p] = e;
    }
}

// ---------------- relation branch (tiny: R=32), 1 block / 256 threads ----------------
__global__ void k_rel(const float* __restrict__ rel_feat, const float* __restrict__ W_rel,
                      const float* __restrict__ attn_r,
                      const float* __restrict__ lng, const float* __restrict__ lnb) {
    __shared__ float rn[RRR * DIN];
    __shared__ float frel[RRR * HD];
    int tid = threadIdx.x;
    for (int i = tid; i < RRR * DIN; i += 256) rn[i] = rel_feat[i];
    __syncthreads();
    int w = tid >> 5, lane = tid & 31;
    for (int rr = 0; rr < 4; rr++) {
        int r = w * 4 + rr;
        float s = 0.f, sq = 0.f;
        for (int j = lane; j < DIN; j += 32) { float v = rn[r * DIN + j]; s += v; sq += v * v; }
        for (int o = 16; o; o >>= 1) {
            s  += __shfl_xor_sync(~0u, s, o);
            sq += __shfl_xor_sync(~0u, sq, o);
        }
        float m  = s / DIN;
        float sc = rsqrtf(sq / DIN - m * m + 1e-5f);
        for (int j = lane; j < DIN; j += 32)
            rn[r * DIN + j] = (rn[r * DIN + j] - m) * sc * lng[j] + lnb[j];
    }
    __syncthreads();
    for (int i = tid; i < RRR * HD; i += 256) {
        int r = i / HD, j = i % HD;
        float acc = 0.f;
        for (int k = 0; k < DIN; k++) acc += rn[r * DIN + k] * W_rel[k * HD + j];
        frel[i] = acc;
    }
    __syncthreads();
    if (tid < RRR * HHH) {
        int r = tid / HHH, h = tid % HHH;
        float acc = 0.f;
        for (int d = 0; d < DDD; d++) acc += frel[r * HD + h * DDD + d] * attn_r[h * DDD + d];
        g_er[tid] = acc;
    }
}

// ---------------- LN(ent) + 3 projections (M-tile=64, 256 threads) ----------------
__global__ void k_proj(const float* __restrict__ ent,
                       const float* __restrict__ Wh, const float* __restrict__ Wt,
                       const float* __restrict__ We,
                       const float* __restrict__ lng, const float* __restrict__ lnb) {
    extern __shared__ float sm[];
    float* xs = sm;                // 64*128
    float* ws = sm + 64 * 128;     // 128*128
    int tid = threadIdx.x;
    int bm  = blockIdx.x * 64;

    for (int i = tid; i < 2048; i += 256) {          // float4 granularity
        int r = bm + (i >> 5);
        float4 v = {0.f, 0.f, 0.f, 0.f};
        if (r < NN) v = ((const float4*)ent)[r * 32 + (i & 31)];
        ((float4*)xs)[i] = v;
    }
    __syncthreads();

    int w = tid >> 5, lane = tid & 31;
    for (int rr = 0; rr < 8; rr++) {
        int r = w * 8 + rr;
        float v0 = xs[r * 128 + lane], v1 = xs[r * 128 + lane + 32],
              v2 = xs[r * 128 + lane + 64], v3 = xs[r * 128 + lane + 96];
        float s = v0 + v1 + v2 + v3;
        float sq = v0 * v0 + v1 * v1 + v2 * v2 + v3 * v3;
        for (int o = 16; o; o >>= 1) {
            s  += __shfl_xor_sync(~0u, s, o);
            sq += __shfl_xor_sync(~0u, sq, o);
        }
        float m  = s * (1.f / 128.f);
        float sc = rsqrtf(sq * (1.f / 128.f) - m * m + 1e-5f);
        xs[r * 128 + lane]      = (v0 - m) * sc * lng[lane]      + lnb[lane];
        xs[r * 128 + lane + 32] = (v1 - m) * sc * lng[lane + 32] + lnb[lane + 32];
        xs[r * 128 + lane + 64] = (v2 - m) * sc * lng[lane + 64] + lnb[lane + 64];
        xs[r * 128 + lane + 96] = (v3 - m) * sc * lng[lane + 96] + lnb[lane + 96];
    }
    __syncthreads();

    int tx = tid & 31, ty = tid >> 5;
    const float* Ws[3] = {Wh, Wt, We};
    float* Os[3] = {g_fhead, g_ftail, g_fent};
    for (int wi = 0; wi < 3; wi++) {
        for (int i = tid; i < 4096; i += 256)
            ((float4*)ws)[i] = ((const float4*)Ws[wi])[i];
        __syncthreads();
        float acc[8][4];
        #pragma unroll
        for (int im = 0; im < 8; im++) { acc[im][0]=acc[im][1]=acc[im][2]=acc[im][3]=0.f; }
        for (int k = 0; k < 128; k++) {
            float4 bv = ((float4*)(ws + k * 128))[tx];
            #pragma unroll
            for (int im = 0; im < 8; im++) {
                float av = xs[(ty * 8 + im) * 128 + k];
                acc[im][0] += av * bv.x; acc[im][1] += av * bv.y;
                acc[im][2] += av * bv.z; acc[im][3] += av * bv.w;
            }
        }
        #pragma unroll
        for (int im = 0; im < 8; im++) {
            int r = bm + ty * 8 + im;
            if (r < NN) {
                float4 o = {acc[im][0], acc[im][1], acc[im][2], acc[im][3]};
                ((float4*)(Os[wi] + r * 128))[tx] = o;
            }
        }
        __syncthreads();
    }
}

// ---------------- edge scores + segment softmax (warp per dst node) ----------------
__global__ void k_scores(const int* __restrict__ src, const int* __restrict__ rid) {
    int warp = (blockIdx.x * blockDim.x + threadIdx.x) >> 5;
    if (warp >= NN) return;
    int lane = threadIdx.x & 31;
    int h = lane >> 2, kk = lane & 3;
    int d = warp;
    float4 t = ((const float4*)(g_ftail + d * 128))[lane];
    int r0 = g_rowptr[d], r1 = g_rowptr[d + 1];
    float login = g_login[d];
    float m = -1e30f, s = 0.f;
    for (int i = r0; i < r1; i++) {
        int eid = g_eperm[i];
        int sn = src[eid];
        int rv = rid[eid];
        float4 hh = ((const float4*)(g_fhead + sn * 128))[lane];
        float p = hh.x * t.x + hh.y * t.y + hh.z * t.z + hh.w * t.w;
        p += __shfl_xor_sync(~0u, p, 1);
        p += __shfl_xor_sync(~0u, p, 2);       // full 16-dot on all 4 lanes of head h
        float e = p * g_er[rv * 8 + h] * login;
        if (kk == 0) g_attn[eid * 8 + h] = e;
        float mn = fmaxf(m, e);
        s = s * __expf(m - mn) + __expf(e - mn);
        m = mn;
    }
    float inv = 1.f / s;
    for (int i = r0; i < r1; i++) {
        int eid = g_eperm[i];
        if (kk == 0) {
            float e = g_attn[eid * 8 + h];
            g_attn[eid * 8 + h] = __expf(e - m) * inv;
        }
    }
}

// ---------------- one PPR diffusion hop (warp per dst node) ----------------
__global__ void k_diff(int iter, const int* __restrict__ src) {
    const float* fin;
    float* fout;
    if (iter == 0)      { fin = g_fent;  fout = g_featA; }
    else if (iter & 1)  { fin = g_featA; fout = g_featB; }
    else                { fin = g_featB; fout = g_featA; }
    int warp = (blockIdx.x * blockDim.x + threadIdx.x) >> 5;
    if (warp >= NN) return;
    int lane = threadIdx.x & 31;
    int d = warp;
    int r0 = g_rowptr[d], r1 = g_rowptr[d + 1];
    int hsel = lane >> 2;
    float4 acc = {0.f, 0.f, 0.f, 0.f};
    for (int i = r0; i < r1; i++) {
        int eid = g_eperm[i];
        int sn = src[eid];
        float a = g_attn[eid * 8 + hsel];
        float4 f = ((const float4*)(fin + sn * 128))[lane];
        acc.x += f.x * a; acc.y += f.y * a; acc.z += f.z * a; acc.w += f.w * a;
    }
    float4 fe = ((const float4*)(g_fent + d * 128))[lane];
    float4 o;
    o.x = 0.9f * acc.x + 0.1f * fe.x;
    o.y = 0.9f * acc.y + 0.1f * fe.y;
    o.z = 0.9f * acc.z + 0.1f * fe.z;
    o.w = 0.9f * acc.w + 0.1f * fe.w;
    ((float4*)(fout + d * 128))[lane] = o;
}

// ---------------- residual + LN + FFN + residual (M-tile=64, 192KB smem) ----------------
__global__ void k_final(const float* __restrict__ ent,
                        const float* __restrict__ ffg, const float* __restrict__ ffb,
                        const float* __restrict__ W1, const float* __restrict__ b1,
                        const float* __restrict__ W2, const float* __restrict__ b2,
                        float* __restrict__ out) {
    extern __shared__ float sm[];
    float* hs  = sm;             // 64*128 LN(rst)
    float* w1s = sm + 8192;      // 128*128 chunk
    float* w2s = w1s + 16384;    // 128*128 chunk
    float* hid = w2s + 16384;    // 64*128
    int tid = threadIdx.x;
    int bm  = blockIdx.x * 64;

    for (int i = tid; i < 2048; i += 256) {
        int r = bm + (i >> 5);
        float4 v = {0.f, 0.f, 0.f, 0.f};
        if (r < NN) {
            float4 fa = ((const float4*)g_featA)[r * 32 + (i & 31)];
            float4 en = ((const float4*)ent)[r * 32 + (i & 31)];
            v.x = fa.x + en.x; v.y = fa.y + en.y; v.z = fa.z + en.z; v.w = fa.w + en.w;
        }
        ((float4*)hs)[i] = v;
    }
    __syncthreads();

    int w = tid >> 5, lane = tid & 31;
    for (int rr = 0; rr < 8; rr++) {
        int r = w * 8 + rr;
        float v0 = hs[r * 128 + lane], v1 = hs[r * 128 + lane + 32],
              v2 = hs[r * 128 + lane + 64], v3 = hs[r * 128 + lane + 96];
        float s = v0 + v1 + v2 + v3;
        float sq = v0 * v0 + v1 * v1 + v2 * v2 + v3 * v3;
        for (int o = 16; o; o >>= 1) {
            s  += __shfl_xor_sync(~0u, s, o);
            sq += __shfl_xor_sync(~0u, sq, o);
        }
        float m  = s * (1.f / 128.f);
        float sc = rsqrtf(sq * (1.f / 128.f) - m * m + 1e-5f);
        hs[r * 128 + lane]      = (v0 - m) * sc * ffg[lane]      + ffb[lane];
        hs[r * 128 + lane + 32] = (v1 - m) * sc * ffg[lane + 32] + ffb[lane + 32];
        hs[r * 128 + lane + 64] = (v2 - m) * sc * ffg[lane + 64] + ffb[lane + 64];
        hs[r * 128 + lane + 96] = (v3 - m) * sc * ffg[lane + 96] + ffb[lane + 96];
    }
    __syncthreads();

    int tx = tid & 31, ty = tid >> 5;
    float oacc[8][4];
    #pragma unroll
    for (int im = 0; im < 8; im++) { oacc[im][0]=oacc[im][1]=oacc[im][2]=oacc[im][3]=0.f; }

    for (int c = 0; c < 4; c++) {
        for (int i = tid; i < 4096; i += 256) {      // W1 chunk [128 x 128]
            int k = i >> 5, j4 = i & 31;
            ((float4*)w1s)[i] = ((const float4*)(W1 + k * 512 + c * 128))[j4];
        }
        for (int i = tid; i < 4096; i += 256) {      // W2 chunk [128 x 128]
            int j = i >> 5, o4 = i & 31;
            ((float4*)w2s)[i] = ((const float4*)(W2 + (c * 128 + j) * 128))[o4];
        }
        __syncthreads();

        float4 b1v = ((const float4*)(b1 + c * 128))[tx];
        float hacc[8][4];
        #pragma unroll
        for (int im = 0; im < 8; im++) {
            hacc[im][0] = b1v.x; hacc[im][1] = b1v.y; hacc[im][2] = b1v.z; hacc[im][3] = b1v.w;
        }
        for (int k = 0; k < 128; k++) {
            float4 bv = ((float4*)(w1s + k * 128))[tx];
            #pragma unroll
            for (int im = 0; im < 8; im++) {
                float av = hs[(ty * 8 + im) * 128 + k];
                hacc[im][0] += av * bv.x; hacc[im][1] += av * bv.y;
                hacc[im][2] += av * bv.z; hacc[im][3] += av * bv.w;
            }
        }
        #pragma unroll
        for (int im = 0; im < 8; im++) {
            float4 hv;
            hv.x = fmaxf(hacc[im][0], 0.f); hv.y = fmaxf(hacc[im][1], 0.f);
            hv.z = fmaxf(hacc[im][2], 0.f); hv.w = fmaxf(hacc[im][3], 0.f);
            ((float4*)(hid + (ty * 8 + im) * 128))[tx] = hv;
        }
        __syncthreads();

        for (int k = 0; k < 128; k++) {
            float4 bv = ((float4*)(w2s + k * 128))[tx];
            #pragma unroll
            for (int im = 0; im < 8; im++) {
                float av = hid[(ty * 8 + im) * 128 + k];
                oacc[im][0] += av * bv.x; oacc[im][1] += av * bv.y;
                oacc[im][2] += av * bv.z; oacc[im][3] += av * bv.w;
            }
        }
        __syncthreads();
    }

    float4 b2v = ((const float4*)b2)[tx];
    #pragma unroll
    for (int im = 0; im < 8; im++) {
        int r = bm + ty * 8 + im;
        if (r < NN) {
            float4 fa = ((const float4*)(g_featA + r * 128))[tx];
            float4 en = ((const float4*)(ent + r * 128))[tx];
            float4 o;
            o.x = oacc[im][0] + b2v.x + fa.x + en.x;
            o.y = oacc[im][1] + b2v.y + fa.y + en.y;
            o.z = oacc[im][2] + b2v.z + fa.z + en.z;
            o.w = oacc[im][3] + b2v.w + fa.w + en.w;
            ((float4*)(out + r * 128))[tx] = o;
        }
    }
}

// ---------------- launch ----------------
extern "C" void kernel_launch(void* const* d_in, const int* in_sizes, int n_in,
                              void* d_out, int out_size) {
    const float* ent    = (const float*)d_in[0];
    const float* rel    = (const float*)d_in[1];
    const int*   src    = (const int*)  d_in[2];
    const int*   dst    = (const int*)  d_in[3];
    const int*   rid    = (const int*)  d_in[4];
    const float* Wh     = (const float*)d_in[5];
    const float* Wt     = (const float*)d_in[6];
    const float* We     = (const float*)d_in[7];
    const float* Wr     = (const float*)d_in[8];
    const float* attn_r = (const float*)d_in[9];
    const float* lng    = (const float*)d_in[10];
    const float* lnb    = (const float*)d_in[11];
    const float* lrg    = (const float*)d_in[12];
    const float* lrb    = (const float*)d_in[13];
    const float* ffg    = (const float*)d_in[14];
    const float* ffb    = (const float*)d_in[15];
    const float* W1     = (const float*)d_in[16];
    const float* b1     = (const float*)d_in[17];
    const float* W2     = (const float*)d_in[18];
    const float* b2     = (const float*)d_in[19];
    float* out = (float*)d_out;

    cudaFuncSetAttribute(k_proj,  cudaFuncAttributeMaxDynamicSharedMemorySize, 96 * 1024);
    cudaFuncSetAttribute(k_final, cudaFuncAttributeMaxDynamicSharedMemorySize, 192 * 1024);

    k_zero_deg<<<(NN + 255) / 256, 256>>>();
    k_hist<<<(EE + 255) / 256, 256>>>(dst);
    k_scan<<<1, 1024>>>();
    k_scatter<<<(EE + 255) / 256, 256>>>(dst);
    k_rel<<<1, 256>>>(rel, Wr, attn_r, lrg, lrb);
    k_proj<<<(NN + 63) / 64, 256, 96 * 1024>>>(ent, Wh, Wt, We, lng, lnb);
    k_scores<<<(NN + 7) / 8, 256>>>(src, rid);
    for (int it = 0; it < 5; it++)
        k_diff<<<(NN + 7) / 8, 256>>>(it, src);
    k_final<<<(NN + 63) / 64, 256, 192 * 1024>>>(ent, ffg, ffb, W1, b1, W2, b2, out);
}

// round 2
// speedup vs baseline: 1.3485x; 1.3485x over previous
#include <cuda_runtime.h>
#include <math.h>
#include <stdint.h>

#define NN   50000
#define EE   800000
#define RRR  32
#define DIN  128
#define HHH  8
#define DDD  16
#define HD   128

// ---------------- device scratch ----------------
__device__ float g_fhead[NN * HD];
__device__ float g_ftail[NN * HD];
__device__ float g_fent [NN * HD];
__device__ float g_featA[NN * HD];
__device__ float g_featB[NN * HD];
__device__ float g_attn [EE * HHH];      // CSR-position-ordered attention
__device__ float g_er   [RRR * HHH];
__device__ float g_login[NN];
__device__ int   g_deg   [NN];
__device__ int   g_rowptr[NN + 1];
__device__ int   g_cursor[NN];
__device__ int   g_esrc  [EE];           // src node id, CSR order
__device__ int   g_erid  [EE];           // relation id, CSR order

// ---------------- CSR build ----------------
__global__ void k_zero_deg() {
    int i = blockIdx.x * blockDim.x + threadIdx.x;
    if (i < NN) g_deg[i] = 0;
}

__global__ void k_hist(const int* __restrict__ dst) {
    int e = blockIdx.x * blockDim.x + threadIdx.x;
    if (e < EE) atomicAdd(&g_deg[dst[e]], 1);
}

__global__ void k_scan() {   // 1 block, 1024 threads
    __shared__ int sums[1024];
    int tid = threadIdx.x;
    const int C = (NN + 1023) / 1024;
    int start = tid * C;
    int end   = min(start + C, NN);
    int s = 0;
    for (int i = start; i < end; i++) s += g_deg[i];
    sums[tid] = s;
    __syncthreads();
    for (int off = 1; off < 1024; off <<= 1) {
        int v = (tid >= off) ? sums[tid - off] : 0;
        __syncthreads();
        sums[tid] += v;
        __syncthreads();
    }
    int base = (tid == 0) ? 0 : sums[tid - 1];
    for (int i = start; i < end; i++) {
        g_rowptr[i] = base;
        int d = g_deg[i];
        g_login[i] = logf((float)max(d, 1)) * 0.25f;   // /sqrt(16)
        g_cursor[i] = 0;
        base += d;
    }
    if (tid == 1023) g_rowptr[NN] = sums[1023];
}

__global__ void k_scatter(const int* __restrict__ dst, const int* __restrict__ src,
                          const int* __restrict__ rid) {
    int e = blockIdx.x * blockDim.x + threadIdx.x;
    if (e < EE) {
        int d = dst[e];
        int p = atomicAdd(&g_cursor[d], 1);
        int pos = g_rowptr[d] + p;
        g_esrc[pos] = src[e];
        g_erid[pos] = rid[e];
    }
}

// ---------------- relation branch ----------------
__global__ void k_rel(const float* __restrict__ rel_feat, const float* __restrict__ W_rel,
                      const float* __restrict__ attn_r,
                      const float* __restrict__ lng, const float* __restrict__ lnb) {
    __shared__ float rn[RRR * DIN];
    __shared__ float frel[RRR * HD];
    int tid = threadIdx.x;
    for (int i = tid; i < RRR * DIN; i += 256) rn[i] = rel_feat[i];
    __syncthreads();
    int w = tid >> 5, lane = tid & 31;
    for (int rr = 0; rr < 4; rr++) {
        int r = w * 4 + rr;
        float s = 0.f, sq = 0.f;
        for (int j = lane; j < DIN; j += 32) { float v = rn[r * DIN + j]; s += v; sq += v * v; }
        for (int o = 16; o; o >>= 1) {
            s  += __shfl_xor_sync(~0u, s, o);
            sq += __shfl_xor_sync(~0u, sq, o);
        }
        float m  = s / DIN;
        float sc = rsqrtf(sq / DIN - m * m + 1e-5f);
        for (int j = lane; j < DIN; j += 32)
            rn[r * DIN + j] = (rn[r * DIN + j] - m) * sc * lng[j] + lnb[j];
    }
    __syncthreads();
    for (int i = tid; i < RRR * HD; i += 256) {
        int r = i / HD, j = i % HD;
        float acc = 0.f;
        for (int k = 0; k < DIN; k++) acc += rn[r * DIN + k] * W_rel[k * HD + j];
        frel[i] = acc;
    }
    __syncthreads();
    if (tid < RRR * HHH) {
        int r = tid / HHH, h = tid % HHH;
        float acc = 0.f;
        for (int d = 0; d < DDD; d++) acc += frel[r * HD + h * DDD + d] * attn_r[h * DDD + d];
        g_er[tid] = acc;
    }
}

// ---------------- LN(ent) + 3 projections (fp32, M-tile 64) ----------------
__global__ void k_proj(const float* __restrict__ ent,
                       const float* __restrict__ Wh, const float* __restrict__ Wt,
                       const float* __restrict__ We,
                       const float* __restrict__ lng, const float* __restrict__ lnb) {
    extern __shared__ float sm[];
    float* xs = sm;                // 64*128
    float* ws = sm + 64 * 128;     // 128*128
    int tid = threadIdx.x;
    int bm  = blockIdx.x * 64;

    for (int i = tid; i < 2048; i += 256) {
        int r = bm + (i >> 5);
        float4 v = {0.f, 0.f, 0.f, 0.f};
        if (r < NN) v = ((const float4*)ent)[r * 32 + (i & 31)];
        ((float4*)xs)[i] = v;
    }
    __syncthreads();

    int w = tid >> 5, lane = tid & 31;
    for (int rr = 0; rr < 8; rr++) {
        int r = w * 8 + rr;
        float v0 = xs[r * 128 + lane], v1 = xs[r * 128 + lane + 32],
              v2 = xs[r * 128 + lane + 64], v3 = xs[r * 128 + lane + 96];
        float s = v0 + v1 + v2 + v3;
        float sq = v0 * v0 + v1 * v1 + v2 * v2 + v3 * v3;
        for (int o = 16; o; o >>= 1) {
            s  += __shfl_xor_sync(~0u, s, o);
            sq += __shfl_xor_sync(~0u, sq, o);
        }
        float m  = s * (1.f / 128.f);
        float sc = rsqrtf(sq * (1.f / 128.f) - m * m + 1e-5f);
        xs[r * 128 + lane]      = (v0 - m) * sc * lng[lane]      + lnb[lane];
        xs[r * 128 + lane + 32] = (v1 - m) * sc * lng[lane + 32] + lnb[lane + 32];
        xs[r * 128 + lane + 64] = (v2 - m) * sc * lng[lane + 64] + lnb[lane + 64];
        xs[r * 128 + lane + 96] = (v3 - m) * sc * lng[lane + 96] + lnb[lane + 96];
    }
    __syncthreads();

    int tx = tid & 31, ty = tid >> 5;
    const float* Ws[3] = {Wh, Wt, We};
    float* Os[3] = {g_fhead, g_ftail, g_fent};
    for (int wi = 0; wi < 3; wi++) {
        for (int i = tid; i < 4096; i += 256)
            ((float4*)ws)[i] = ((const float4*)Ws[wi])[i];
        __syncthreads();
        float acc[8][4];
        #pragma unroll
        for (int im = 0; im < 8; im++) { acc[im][0]=acc[im][1]=acc[im][2]=acc[im][3]=0.f; }
        for (int k = 0; k < 128; k++) {
            float4 bv = ((float4*)(ws + k * 128))[tx];
            #pragma unroll
            for (int im = 0; im < 8; im++) {
                float av = xs[(ty * 8 + im) * 128 + k];
                acc[im][0] += av * bv.x; acc[im][1] += av * bv.y;
                acc[im][2] += av * bv.z; acc[im][3] += av * bv.w;
            }
        }
        #pragma unroll
        for (int im = 0; im < 8; im++) {
            int r = bm + ty * 8 + im;
            if (r < NN) {
                float4 o = {acc[im][0], acc[im][1], acc[im][2], acc[im][3]};
                ((float4*)(Os[wi] + r * 128))[tx] = o;
            }
        }
        __syncthreads();
    }
}

// ---------------- edge scores + segment softmax (warp per dst, unroll-4) ----------------
__global__ void k_scores() {
    int warp = (blockIdx.x * blockDim.x + threadIdx.x) >> 5;
    if (warp >= NN) return;
    int lane = threadIdx.x & 31;
    int h = lane >> 2, kk = lane & 3;
    int d = warp;
    float4 t = ((const float4*)(g_ftail + d * 128))[lane];
    int r0 = g_rowptr[d], r1 = g_rowptr[d + 1];
    float login = g_login[d];
    float m = -1e30f, s = 0.f;

    int i = r0;
    for (; i + 4 <= r1; i += 4) {
        int sn0 = g_esrc[i],   sn1 = g_esrc[i+1], sn2 = g_esrc[i+2], sn3 = g_esrc[i+3];
        int rv0 = g_erid[i],   rv1 = g_erid[i+1], rv2 = g_erid[i+2], rv3 = g_erid[i+3];
        float4 h0 = ((const float4*)(g_fhead + (size_t)sn0 * 128))[lane];
        float4 h1 = ((const float4*)(g_fhead + (size_t)sn1 * 128))[lane];
        float4 h2 = ((const float4*)(g_fhead + (size_t)sn2 * 128))[lane];
        float4 h3 = ((const float4*)(g_fhead + (size_t)sn3 * 128))[lane];
        float p0 = h0.x*t.x + h0.y*t.y + h0.z*t.z + h0.w*t.w;
        float p1 = h1.x*t.x + h1.y*t.y + h1.z*t.z + h1.w*t.w;
        float p2 = h2.x*t.x + h2.y*t.y + h2.z*t.z + h2.w*t.w;
        float p3 = h3.x*t.x + h3.y*t.y + h3.z*t.z + h3.w*t.w;
        p0 += __shfl_xor_sync(~0u, p0, 1); p0 += __shfl_xor_sync(~0u, p0, 2);
        p1 += __shfl_xor_sync(~0u, p1, 1); p1 += __shfl_xor_sync(~0u, p1, 2);
        p2 += __shfl_xor_sync(~0u, p2, 1); p2 += __shfl_xor_sync(~0u, p2, 2);
        p3 += __shfl_xor_sync(~0u, p3, 1); p3 += __shfl_xor_sync(~0u, p3, 2);
        float e0 = p0 * g_er[rv0 * 8 + h] * login;
        float e1 = p1 * g_er[rv1 * 8 + h] * login;
        float e2 = p2 * g_er[rv2 * 8 + h] * login;
        float e3 = p3 * g_er[rv3 * 8 + h] * login;
        if (kk == 0) {
            g_attn[(size_t)(i  ) * 8 + h] = e0;
            g_attn[(size_t)(i+1) * 8 + h] = e1;
            g_attn[(size_t)(i+2) * 8 + h] = e2;
            g_attn[(size_t)(i+3) * 8 + h] = e3;
        }
        float mn;
        mn = fmaxf(m, e0); s = s * __expf(m - mn) + __expf(e0 - mn); m = mn;
        mn = fmaxf(m, e1); s = s * __expf(m - mn) + __expf(e1 - mn); m = mn;
        mn = fmaxf(m, e2); s = s * __expf(m - mn) + __expf(e2 - mn); m = mn;
        mn = fmaxf(m, e3); s = s * __expf(m - mn) + __expf(e3 - mn); m = mn;
    }
    for (; i < r1; i++) {
        int sn = g_esrc[i];
        int rv = g_erid[i];
        float4 hh = ((const float4*)(g_fhead + (size_t)sn * 128))[lane];
        float p = hh.x*t.x + hh.y*t.y + hh.z*t.z + hh.w*t.w;
        p += __shfl_xor_sync(~0u, p, 1);
        p += __shfl_xor_sync(~0u, p, 2);
        float e = p * g_er[rv * 8 + h] * login;
        if (kk == 0) g_attn[(size_t)i * 8 + h] = e;
        float mn = fmaxf(m, e);
        s = s * __expf(m - mn) + __expf(e - mn);
        m = mn;
    }
    float inv = 1.f / s;
    if (kk == 0) {
        for (int j = r0; j < r1; j++) {
            float e = g_attn[(size_t)j * 8 + h];
            g_attn[(size_t)j * 8 + h] = __expf(e - m) * inv;
        }
    }
}

// ---------------- one PPR diffusion hop (warp per dst, unroll-4) ----------------
__global__ void k_diff(int iter) {
    const float* fin;
    float* fout;
    if (iter == 0)      { fin = g_fent;  fout = g_featA; }
    else if (iter & 1)  { fin = g_featA; fout = g_featB; }
    else                { fin = g_featB; fout = g_featA; }
    int warp = (blockIdx.x * blockDim.x + threadIdx.x) >> 5;
    if (warp >= NN) return;
    int lane = threadIdx.x & 31;
    int d = warp;
    int r0 = g_rowptr[d], r1 = g_rowptr[d + 1];
    int hsel = lane >> 2;
    float4 acc = {0.f, 0.f, 0.f, 0.f};

    int i = r0;
    for (; i + 4 <= r1; i += 4) {
        int sn0 = g_esrc[i], sn1 = g_esrc[i+1], sn2 = g_esrc[i+2], sn3 = g_esrc[i+3];
        float a0 = g_attn[(size_t)(i  ) * 8 + hsel];
        float a1 = g_attn[(size_t)(i+1) * 8 + hsel];
        float a2 = g_attn[(size_t)(i+2) * 8 + hsel];
        float a3 = g_attn[(size_t)(i+3) * 8 + hsel];
        float4 f0 = ((const float4*)(fin + (size_t)sn0 * 128))[lane];
        float4 f1 = ((const float4*)(fin + (size_t)sn1 * 128))[lane];
        float4 f2 = ((const float4*)(fin + (size_t)sn2 * 128))[lane];
        float4 f3 = ((const float4*)(fin + (size_t)sn3 * 128))[lane];
        acc.x += f0.x*a0 + f1.x*a1 + f2.x*a2 + f3.x*a3;
        acc.y += f0.y*a0 + f1.y*a1 + f2.y*a2 + f3.y*a3;
        acc.z += f0.z*a0 + f1.z*a1 + f2.z*a2 + f3.z*a3;
        acc.w += f0.w*a0 + f1.w*a1 + f2.w*a2 + f3.w*a3;
    }
    for (; i < r1; i++) {
        int sn = g_esrc[i];
        float a = g_attn[(size_t)i * 8 + hsel];
        float4 f = ((const float4*)(fin + (size_t)sn * 128))[lane];
        acc.x += f.x * a; acc.y += f.y * a; acc.z += f.z * a; acc.w += f.w * a;
    }
    float4 fe = ((const float4*)(g_fent + d * 128))[lane];
    float4 o;
    o.x = 0.9f * acc.x + 0.1f * fe.x;
    o.y = 0.9f * acc.y + 0.1f * fe.y;
    o.z = 0.9f * acc.z + 0.1f * fe.z;
    o.w = 0.9f * acc.w + 0.1f * fe.w;
    ((float4*)(fout + d * 128))[lane] = o;
}

// ---------------- tf32 helpers ----------------
__device__ __forceinline__ uint32_t f2tf(float x) {
    uint32_t r;
    asm("cvt.rna.tf32.f32 %0, %1;" : "=r"(r) : "f"(x));
    return r;
}
__device__ __forceinline__ void mma_tf32(float c[4], uint32_t a0, uint32_t a1,
                                         uint32_t a2, uint32_t a3,
                                         uint32_t b0, uint32_t b1) {
    asm volatile(
        "mma.sync.aligned.m16n8k8.row.col.f32.tf32.tf32.f32 "
        "{%0,%1,%2,%3}, {%4,%5,%6,%7}, {%8,%9}, {%0,%1,%2,%3};\n"
        : "+f"(c[0]), "+f"(c[1]), "+f"(c[2]), "+f"(c[3])
        : "r"(a0), "r"(a1), "r"(a2), "r"(a3), "r"(b0), "r"(b1));
}

// ---------------- residual + LN + FFN + residual (tf32 tensor cores) ----------------
// smem: hs[64][132] tf32, w1s[128][132] tf32, w2s[128][132] tf32, hid[64][132] tf32
#define LDA 132
__global__ void __launch_bounds__(256, 1)
k_final(const float* __restrict__ ent,
        const float* __restrict__ ffg, const float* __restrict__ ffb,
        const float* __restrict__ W1, const float* __restrict__ b1,
        const float* __restrict__ W2, const float* __restrict__ b2,
        float* __restrict__ out) {
    extern __shared__ float sm[];
    float* hs  = sm;                       // 64*132
    float* w1s = hs  + 64 * LDA;           // 128*132
    float* w2s = w1s + 128 * LDA;          // 128*132
    float* hid = w2s + 128 * LDA;          // 64*132
    int tid = threadIdx.x;
    int bm  = blockIdx.x * 64;
    int lane = tid & 31;
    int wid  = tid >> 5;
    int rg = wid & 3;              // row group: rows rg*16 .. rg*16+15
    int cg = wid >> 2;             // col group: cols cg*64 .. cg*64+63
    int g  = lane >> 2;            // 0..7
    int tg = lane & 3;             // 0..3

    // load rst = featA + ent, fp32 into hs
    for (int i = tid; i < 2048; i += 256) {
        int r = bm + (i >> 5);
        float4 v = {0.f, 0.f, 0.f, 0.f};
        if (r < NN) {
            float4 fa = ((const float4*)g_featA)[(size_t)r * 32 + (i & 31)];
            float4 en = ((const float4*)ent)[(size_t)r * 32 + (i & 31)];
            v.x = fa.x + en.x; v.y = fa.y + en.y; v.z = fa.z + en.z; v.w = fa.w + en.w;
        }
        ((float4*)(hs + (i >> 5) * LDA))[i & 31] = v;
    }
    __syncthreads();

    // LayerNorm rows, write back tf32-rounded
    for (int rr = 0; rr < 8; rr++) {
        int r = wid * 8 + rr;
        float v0 = hs[r * LDA + lane],       v1 = hs[r * LDA + lane + 32],
              v2 = hs[r * LDA + lane + 64],  v3 = hs[r * LDA + lane + 96];
        float s = v0 + v1 + v2 + v3;
        float sq = v0*v0 + v1*v1 + v2*v2 + v3*v3;
        for (int o = 16; o; o >>= 1) {
            s  += __shfl_xor_sync(~0u, s, o);
            sq += __shfl_xor_sync(~0u, sq, o);
        }
        float mu = s * (1.f / 128.f);
        float sc = rsqrtf(sq * (1.f / 128.f) - mu * mu + 1e-5f);
        hs[r * LDA + lane]      = __uint_as_float(f2tf((v0 - mu) * sc * ffg[lane]      + ffb[lane]));
        hs[r * LDA + lane + 32] = __uint_as_float(f2tf((v1 - mu) * sc * ffg[lane + 32] + ffb[lane + 32]));
        hs[r * LDA + lane + 64] = __uint_as_float(f2tf((v2 - mu) * sc * ffg[lane + 64] + ffb[lane + 64]));
        hs[r * LDA + lane + 96] = __uint_as_float(f2tf((v3 - mu) * sc * ffg[lane + 96] + ffb[lane + 96]));
    }
    __syncthreads();

    float oacc[8][4];
    #pragma unroll
    for (int nt = 0; nt < 8; nt++) { oacc[nt][0]=oacc[nt][1]=oacc[nt][2]=oacc[nt][3]=0.f; }

    for (int c = 0; c < 4; c++) {
        // load W1 chunk [128 x 128] (cols c*128..) and W2 chunk (rows c*128..), tf32
        for (int i = tid; i < 4096; i += 256) {
            int k = i >> 5, j4 = i & 31;
            float4 v = ((const float4*)(W1 + (size_t)k * 512 + c * 128))[j4];
            float4 o;
            o.x = __uint_as_float(f2tf(v.x)); o.y = __uint_as_float(f2tf(v.y));
            o.z = __uint_as_float(f2tf(v.z)); o.w = __uint_as_float(f2tf(v.w));
            ((float4*)(w1s + k * LDA))[j4] = o;
        }
        for (int i = tid; i < 4096; i += 256) {
            int k = i >> 5, j4 = i & 31;
            float4 v = ((const float4*)(W2 + (size_t)(c * 128 + k) * 128))[j4];
            float4 o;
            o.x = __uint_as_float(f2tf(v.x)); o.y = __uint_as_float(f2tf(v.y));
            o.z = __uint_as_float(f2tf(v.z)); o.w = __uint_as_float(f2tf(v.w));
            ((float4*)(w2s + k * LDA))[j4] = o;
        }
        __syncthreads();

        // Stage 1: Hchunk[64x128] = hs[64x128] @ w1s[128x128]; warp: rows rg*16, cols cg*64 (8 n-tiles)
        float hacc[8][4];
        #pragma unroll
        for (int nt = 0; nt < 8; nt++) { hacc[nt][0]=hacc[nt][1]=hacc[nt][2]=hacc[nt][3]=0.f; }
        for (int ks = 0; ks < 16; ks++) {
            int k0 = ks * 8;
            const float* arow0 = hs + (rg * 16 + g) * LDA + k0;
            const float* arow1 = arow0 + 8 * LDA;
            uint32_t a0 = __float_as_uint(arow0[tg]);
            uint32_t a1 = __float_as_uint(arow1[tg]);
            uint32_t a2 = __float_as_uint(arow0[tg + 4]);
            uint32_t a3 = __float_as_uint(arow1[tg + 4]);
            const float* bb0 = w1s + (k0 + tg) * LDA + cg * 64 + g;
            const float* bb1 = bb0 + 4 * LDA;
            #pragma unroll
            for (int nt = 0; nt < 8; nt++) {
                uint32_t b0 = __float_as_uint(bb0[nt * 8]);
                uint32_t b1 = __float_as_uint(bb1[nt * 8]);
                mma_tf32(hacc[nt], a0, a1, a2, a3, b0, b1);
            }
        }
        // bias + relu + store tf32 to hid
        #pragma unroll
        for (int nt = 0; nt < 8; nt++) {
            int col = cg * 64 + nt * 8 + 2 * tg;
            float bb0 = b1[c * 128 + col], bb1 = b1[c * 128 + col + 1];
            float h0 = fmaxf(hacc[nt][0] + bb0, 0.f);
            float h1 = fmaxf(hacc[nt][1] + bb1, 0.f);
            float h2 = fmaxf(hacc[nt][2] + bb0, 0.f);
            float h3 = fmaxf(hacc[nt][3] + bb1, 0.f);
            hid[(rg * 16 + g)     * LDA + col]     = __uint_as_float(f2tf(h0));
            hid[(rg * 16 + g)     * LDA + col + 1] = __uint_as_float(f2tf(h1));
            hid[(rg * 16 + g + 8) * LDA + col]     = __uint_as_float(f2tf(h2));
            hid[(rg * 16 + g + 8) * LDA + col + 1] = __uint_as_float(f2tf(h3));
        }
        __syncthreads();

        // Stage 2: O += Hchunk[64x128] @ w2s[128x128]; warp: rows rg*16, cols cg*64
        for (int ks = 0; ks < 16; ks++) {
            int k0 = ks * 8;
            const float* arow0 = hid + (rg * 16 + g) * LDA + k0;
            const float* arow1 = arow0 + 8 * LDA;
            uint32_t a0 = __float_as_uint(arow0[tg]);
            uint32_t a1 = __float_as_uint(arow1[tg]);
            uint32_t a2 = __float_as_uint(arow0[tg + 4]);
            uint32_t a3 = __float_as_uint(arow1[tg + 4]);
            const float* bb0 = w2s + (k0 + tg) * LDA + cg * 64 + g;
            const float* bb1 = bb0 + 4 * LDA;
            #pragma unroll
            for (int nt = 0; nt < 8; nt++) {
                uint32_t b0 = __float_as_uint(bb0[nt * 8]);
                uint32_t b1 = __float_as_uint(bb1[nt * 8]);
                mma_tf32(oacc[nt], a0, a1, a2, a3, b0, b1);
            }
        }
        __syncthreads();
    }

    // epilogue: + b2 + featA + ent
    #pragma unroll
    for (int nt = 0; nt < 8; nt++) {
        int col = cg * 64 + nt * 8 + 2 * tg;
        float bb0 = b2[col], bb1 = b2[col + 1];
        int r0c = bm + rg * 16 + g;
        int r1c = r0c + 8;
        if (r0c < NN) {
            float2 fa = *(const float2*)(g_featA + (size_t)r0c * 128 + col);
            float2 en = *(const float2*)(ent     + (size_t)r0c * 128 + col);
            float2 o;
            o.x = oacc[nt][0] + bb0 + fa.x + en.x;
            o.y = oacc[nt][1] + bb1 + fa.y + en.y;
            *(float2*)(out + (size_t)r0c * 128 + col) = o;
        }
        if (r1c < NN) {
            float2 fa = *(const float2*)(g_featA + (size_t)r1c * 128 + col);
            float2 en = *(const float2*)(ent     + (size_t)r1c * 128 + col);
            float2 o;
            o.x = oacc[nt][2] + bb0 + fa.x + en.x;
            o.y = oacc[nt][3] + bb1 + fa.y + en.y;
            *(float2*)(out + (size_t)r1c * 128 + col) = o;
        }
    }
}

// ---------------- launch ----------------
extern "C" void kernel_launch(void* const* d_in, const int* in_sizes, int n_in,
                              void* d_out, int out_size) {
    const float* ent    = (const float*)d_in[0];
    const float* rel    = (const float*)d_in[1];
    const int*   src    = (const int*)  d_in[2];
    const int*   dst    = (const int*)  d_in[3];
    const int*   rid    = (const int*)  d_in[4];
    const float* Wh     = (const float*)d_in[5];
    const float* Wt     = (const float*)d_in[6];
    const float* We     = (const float*)d_in[7];
    const float* Wr     = (const float*)d_in[8];
    const float* attn_r = (const float*)d_in[9];
    const float* lng    = (const float*)d_in[10];
    const float* lnb    = (const float*)d_in[11];
    const float* lrg    = (const float*)d_in[12];
    const float* lrb    = (const float*)d_in[13];
    const float* ffg    = (const float*)d_in[14];
    const float* ffb    = (const float*)d_in[15];
    const float* W1     = (const float*)d_in[16];
    const float* b1     = (const float*)d_in[17];
    const float* W2     = (const float*)d_in[18];
    const float* b2     = (const float*)d_in[19];
    float* out = (float*)d_out;

    const int final_smem = (64 * LDA + 128 * LDA + 128 * LDA + 64 * LDA) * 4;  // 202752 B
    cudaFuncSetAttribute(k_proj,  cudaFuncAttributeMaxDynamicSharedMemorySize, 96 * 1024);
    cudaFuncSetAttribute(k_final, cudaFuncAttributeMaxDynamicSharedMemorySize, final_smem);

    k_zero_deg<<<(NN + 255) / 256, 256>>>();
    k_hist<<<(EE + 255) / 256, 256>>>(dst);
    k_scan<<<1, 1024>>>();
    k_scatter<<<(EE + 255) / 256, 256>>>(dst, src, rid);
    k_rel<<<1, 256>>>(rel, Wr, attn_r, lrg, lrb);
    k_proj<<<(NN + 63) / 64, 256, 96 * 1024>>>(ent, Wh, Wt, We, lng, lnb);
    k_scores<<<(NN + 7) / 8, 256>>>();
    for (int it = 0; it < 5; it++)
        k_diff<<<(NN + 7) / 8, 256>>>(it);
    k_final<<<(NN + 63) / 64, 256, final_smem>>>(ent, ffg, ffb, W1, b1, W2, b2, out);
}

// round 3
// speedup vs baseline: 1.3516x; 1.0023x over previous
#include <cuda_runtime.h>
#include <math.h>
#include <stdint.h>

#define NN   50000
#define EE   800000
#define RRR  32
#define DIN  128
#define HHH  8
#define DDD  16
#define HD   128

// ---------------- device scratch ----------------
__device__ float g_fhead[NN * HD];
__device__ float g_ftail[NN * HD];
__device__ float g_fent [NN * HD];
__device__ float g_featA[NN * HD];
__device__ float g_featB[NN * HD];
__device__ float g_attn [EE * HHH];      // CSR-position-ordered attention
__device__ float g_er   [RRR * HHH];
__device__ float g_login[NN];
__device__ int   g_deg   [NN];
__device__ int   g_rowptr[NN + 1];
__device__ int   g_cursor[NN];
__device__ int   g_esrc  [EE];           // src node id, CSR order
__device__ int   g_erid  [EE];           // relation id, CSR order

// ---------------- CSR build ----------------
__global__ void k_zero_deg() {
    int i = blockIdx.x * blockDim.x + threadIdx.x;
    if (i < NN) g_deg[i] = 0;
}

__global__ void k_hist(const int* __restrict__ dst) {
    int e = blockIdx.x * blockDim.x + threadIdx.x;
    if (e < EE) atomicAdd(&g_deg[dst[e]], 1);
}

__global__ void k_scan() {   // 1 block, 1024 threads
    __shared__ int sums[1024];
    int tid = threadIdx.x;
    const int C = (NN + 1023) / 1024;
    int start = tid * C;
    int end   = min(start + C, NN);
    int s = 0;
    for (int i = start; i < end; i++) s += g_deg[i];
    sums[tid] = s;
    __syncthreads();
    for (int off = 1; off < 1024; off <<= 1) {
        int v = (tid >= off) ? sums[tid - off] : 0;
        __syncthreads();
        sums[tid] += v;
        __syncthreads();
    }
    int base = (tid == 0) ? 0 : sums[tid - 1];
    for (int i = start; i < end; i++) {
        g_rowptr[i] = base;
        int d = g_deg[i];
        g_login[i] = logf((float)max(d, 1)) * 0.25f;   // /sqrt(16)
        g_cursor[i] = 0;
        base += d;
    }
    if (tid == 1023) g_rowptr[NN] = sums[1023];
}

__global__ void k_scatter(const int* __restrict__ dst, const int* __restrict__ src,
                          const int* __restrict__ rid) {
    int e = blockIdx.x * blockDim.x + threadIdx.x;
    if (e < EE) {
        int d = dst[e];
        int p = atomicAdd(&g_cursor[d], 1);
        int pos = g_rowptr[d] + p;
        g_esrc[pos] = src[e];
        g_erid[pos] = rid[e];
    }
}

// ---------------- relation branch ----------------
__global__ void k_rel(const float* __restrict__ rel_feat, const float* __restrict__ W_rel,
                      const float* __restrict__ attn_r,
                      const float* __restrict__ lng, const float* __restrict__ lnb) {
    __shared__ float rn[RRR * DIN];
    __shared__ float frel[RRR * HD];
    int tid = threadIdx.x;
    for (int i = tid; i < RRR * DIN; i += 256) rn[i] = rel_feat[i];
    __syncthreads();
    int w = tid >> 5, lane = tid & 31;
    for (int rr = 0; rr < 4; rr++) {
        int r = w * 4 + rr;
        float s = 0.f, sq = 0.f;
        for (int j = lane; j < DIN; j += 32) { float v = rn[r * DIN + j]; s += v; sq += v * v; }
        for (int o = 16; o; o >>= 1) {
            s  += __shfl_xor_sync(~0u, s, o);
            sq += __shfl_xor_sync(~0u, sq, o);
        }
        float m  = s / DIN;
        float sc = rsqrtf(sq / DIN - m * m + 1e-5f);
        for (int j = lane; j < DIN; j += 32)
            rn[r * DIN + j] = (rn[r * DIN + j] - m) * sc * lng[j] + lnb[j];
    }
    __syncthreads();
    for (int i = tid; i < RRR * HD; i += 256) {
        int r = i / HD, j = i % HD;
        float acc = 0.f;
        for (int k = 0; k < DIN; k++) acc += rn[r * DIN + k] * W_rel[k * HD + j];
        frel[i] = acc;
    }
    __syncthreads();
    if (tid < RRR * HHH) {
        int r = tid / HHH, h = tid % HHH;
        float acc = 0.f;
        for (int d = 0; d < DDD; d++) acc += frel[r * HD + h * DDD + d] * attn_r[h * DDD + d];
        g_er[tid] = acc;
    }
}

// ---------------- LN(ent) + 3 projections (fp32, M-tile 64) ----------------
__global__ void k_proj(const float* __restrict__ ent,
                       const float* __restrict__ Wh, const float* __restrict__ Wt,
                       const float* __restrict__ We,
                       const float* __restrict__ lng, const float* __restrict__ lnb) {
    extern __shared__ float sm[];
    float* xs = sm;                // 64*128
    float* ws = sm + 64 * 128;     // 128*128
    int tid = threadIdx.x;
    int bm  = blockIdx.x * 64;

    for (int i = tid; i < 2048; i += 256) {
        int r = bm + (i >> 5);
        float4 v = {0.f, 0.f, 0.f, 0.f};
        if (r < NN) v = ((const float4*)ent)[r * 32 + (i & 31)];
        ((float4*)xs)[i] = v;
    }
    __syncthreads();

    int w = tid >> 5, lane = tid & 31;
    for (int rr = 0; rr < 8; rr++) {
        int r = w * 8 + rr;
        float v0 = xs[r * 128 + lane], v1 = xs[r * 128 + lane + 32],
              v2 = xs[r * 128 + lane + 64], v3 = xs[r * 128 + lane + 96];
        float s = v0 + v1 + v2 + v3;
        float sq = v0 * v0 + v1 * v1 + v2 * v2 + v3 * v3;
        for (int o = 16; o; o >>= 1) {
            s  += __shfl_xor_sync(~0u, s, o);
            sq += __shfl_xor_sync(~0u, sq, o);
        }
        float m  = s * (1.f / 128.f);
        float sc = rsqrtf(sq * (1.f / 128.f) - m * m + 1e-5f);
        xs[r * 128 + lane]      = (v0 - m) * sc * lng[lane]      + lnb[lane];
        xs[r * 128 + lane + 32] = (v1 - m) * sc * lng[lane + 32] + lnb[lane + 32];
        xs[r * 128 + lane + 64] = (v2 - m) * sc * lng[lane + 64] + lnb[lane + 64];
        xs[r * 128 + lane + 96] = (v3 - m) * sc * lng[lane + 96] + lnb[lane + 96];
    }
    __syncthreads();

    int tx = tid & 31, ty = tid >> 5;
    const float* Ws[3] = {Wh, Wt, We};
    float* Os[3] = {g_fhead, g_ftail, g_fent};
    for (int wi = 0; wi < 3; wi++) {
        for (int i = tid; i < 4096; i += 256)
            ((float4*)ws)[i] = ((const float4*)Ws[wi])[i];
        __syncthreads();
        float acc[8][4];
        #pragma unroll
        for (int im = 0; im < 8; im++) { acc[im][0]=acc[im][1]=acc[im][2]=acc[im][3]=0.f; }
        for (int k = 0; k < 128; k++) {
            float4 bv = ((float4*)(ws + k * 128))[tx];
            #pragma unroll
            for (int im = 0; im < 8; im++) {
                float av = xs[(ty * 8 + im) * 128 + k];
                acc[im][0] += av * bv.x; acc[im][1] += av * bv.y;
                acc[im][2] += av * bv.z; acc[im][3] += av * bv.w;
            }
        }
        #pragma unroll
        for (int im = 0; im < 8; im++) {
            int r = bm + ty * 8 + im;
            if (r < NN) {
                float4 o = {acc[im][0], acc[im][1], acc[im][2], acc[im][3]};
                ((float4*)(Os[wi] + r * 128))[tx] = o;
            }
        }
        __syncthreads();
    }
}

// ---------------- edge scores + segment softmax (warp per dst, unroll-4) ----------------
__global__ void k_scores() {
    int warp = (blockIdx.x * blockDim.x + threadIdx.x) >> 5;
    if (warp >= NN) return;
    int lane = threadIdx.x & 31;
    int h = lane >> 2, kk = lane & 3;
    int d = warp;
    float4 t = ((const float4*)(g_ftail + d * 128))[lane];
    int r0 = g_rowptr[d], r1 = g_rowptr[d + 1];
    float login = g_login[d];
    float m = -1e30f, s = 0.f;

    int i = r0;
    for (; i + 4 <= r1; i += 4) {
        int sn0 = g_esrc[i],   sn1 = g_esrc[i+1], sn2 = g_esrc[i+2], sn3 = g_esrc[i+3];
        int rv0 = g_erid[i],   rv1 = g_erid[i+1], rv2 = g_erid[i+2], rv3 = g_erid[i+3];
        float4 h0 = ((const float4*)(g_fhead + (size_t)sn0 * 128))[lane];
        float4 h1 = ((const float4*)(g_fhead + (size_t)sn1 * 128))[lane];
        float4 h2 = ((const float4*)(g_fhead + (size_t)sn2 * 128))[lane];
        float4 h3 = ((const float4*)(g_fhead + (size_t)sn3 * 128))[lane];
        float p0 = h0.x*t.x + h0.y*t.y + h0.z*t.z + h0.w*t.w;
        float p1 = h1.x*t.x + h1.y*t.y + h1.z*t.z + h1.w*t.w;
        float p2 = h2.x*t.x + h2.y*t.y + h2.z*t.z + h2.w*t.w;
        float p3 = h3.x*t.x + h3.y*t.y + h3.z*t.z + h3.w*t.w;
        p0 += __shfl_xor_sync(~0u, p0, 1); p0 += __shfl_xor_sync(~0u, p0, 2);
        p1 += __shfl_xor_sync(~0u, p1, 1); p1 += __shfl_xor_sync(~0u, p1, 2);
        p2 += __shfl_xor_sync(~0u, p2, 1); p2 += __shfl_xor_sync(~0u, p2, 2);
        p3 += __shfl_xor_sync(~0u, p3, 1); p3 += __shfl_xor_sync(~0u, p3, 2);
        float e0 = p0 * g_er[rv0 * 8 + h] * login;
        float e1 = p1 * g_er[rv1 * 8 + h] * login;
        float e2 = p2 * g_er[rv2 * 8 + h] * login;
        float e3 = p3 * g_er[rv3 * 8 + h] * login;
        if (kk == 0) {
            g_attn[(size_t)(i  ) * 8 + h] = e0;
            g_attn[(size_t)(i+1) * 8 + h] = e1;
            g_attn[(size_t)(i+2) * 8 + h] = e2;
            g_attn[(size_t)(i+3) * 8 + h] = e3;
        }
        float mn;
        mn = fmaxf(m, e0); s = s * __expf(m - mn) + __expf(e0 - mn); m = mn;
        mn = fmaxf(m, e1); s = s * __expf(m - mn) + __expf(e1 - mn); m = mn;
        mn = fmaxf(m, e2); s = s * __expf(m - mn) + __expf(e2 - mn); m = mn;
        mn = fmaxf(m, e3); s = s * __expf(m - mn) + __expf(e3 - mn); m = mn;
    }
    for (; i < r1; i++) {
        int sn = g_esrc[i];
        int rv = g_erid[i];
        float4 hh = ((const float4*)(g_fhead + (size_t)sn * 128))[lane];
        float p = hh.x*t.x + hh.y*t.y + hh.z*t.z + hh.w*t.w;
        p += __shfl_xor_sync(~0u, p, 1);
        p += __shfl_xor_sync(~0u, p, 2);
        float e = p * g_er[rv * 8 + h] * login;
        if (kk == 0) g_attn[(size_t)i * 8 + h] = e;
        float mn = fmaxf(m, e);
        s = s * __expf(m - mn) + __expf(e - mn);
        m = mn;
    }
    float inv = 1.f / s;
    if (kk == 0) {
        for (int j = r0; j < r1; j++) {
            float e = g_attn[(size_t)j * 8 + h];
            g_attn[(size_t)j * 8 + h] = __expf(e - m) * inv;
        }
    }
}

// ---------------- one PPR diffusion hop (warp per dst, unroll-4) ----------------
__global__ void k_diff(int iter) {
    const float* fin;
    float* fout;
    if (iter == 0)      { fin = g_fent;  fout = g_featA; }
    else if (iter & 1)  { fin = g_featA; fout = g_featB; }
    else                { fin = g_featB; fout = g_featA; }
    int warp = (blockIdx.x * blockDim.x + threadIdx.x) >> 5;
    if (warp >= NN) return;
    int lane = threadIdx.x & 31;
    int d = warp;
    int r0 = g_rowptr[d], r1 = g_rowptr[d + 1];
    int hsel = lane >> 2;
    float4 acc = {0.f, 0.f, 0.f, 0.f};

    int i = r0;
    for (; i + 4 <= r1; i += 4) {
        int sn0 = g_esrc[i], sn1 = g_esrc[i+1], sn2 = g_esrc[i+2], sn3 = g_esrc[i+3];
        float a0 = g_attn[(size_t)(i  ) * 8 + hsel];
        float a1 = g_attn[(size_t)(i+1) * 8 + hsel];
        float a2 = g_attn[(size_t)(i+2) * 8 + hsel];
        float a3 = g_attn[(size_t)(i+3) * 8 + hsel];
        float4 f0 = ((const float4*)(fin + (size_t)sn0 * 128))[lane];
        float4 f1 = ((const float4*)(fin + (size_t)sn1 * 128))[lane];
        float4 f2 = ((const float4*)(fin + (size_t)sn2 * 128))[lane];
        float4 f3 = ((const float4*)(fin + (size_t)sn3 * 128))[lane];
        acc.x += f0.x*a0 + f1.x*a1 + f2.x*a2 + f3.x*a3;
        acc.y += f0.y*a0 + f1.y*a1 + f2.y*a2 + f3.y*a3;
        acc.z += f0.z*a0 + f1.z*a1 + f2.z*a2 + f3.z*a3;
        acc.w += f0.w*a0 + f1.w*a1 + f2.w*a2 + f3.w*a3;
    }
    for (; i < r1; i++) {
        int sn = g_esrc[i];
        float a = g_attn[(size_t)i * 8 + hsel];
        float4 f = ((const float4*)(fin + (size_t)sn * 128))[lane];
        acc.x += f.x * a; acc.y += f.y * a; acc.z += f.z * a; acc.w += f.w * a;
    }
    float4 fe = ((const float4*)(g_fent + d * 128))[lane];
    float4 o;
    o.x = 0.9f * acc.x + 0.1f * fe.x;
    o.y = 0.9f * acc.y + 0.1f * fe.y;
    o.z = 0.9f * acc.z + 0.1f * fe.z;
    o.w = 0.9f * acc.w + 0.1f * fe.w;
    ((float4*)(fout + d * 128))[lane] = o;
}

// ---------------- tf32 helpers ----------------
__device__ __forceinline__ uint32_t f2tf(float x) {
    uint32_t r;
    asm("cvt.rna.tf32.f32 %0, %1;" : "=r"(r) : "f"(x));
    return r;
}
__device__ __forceinline__ void mma_tf32(float c[4], uint32_t a0, uint32_t a1,
                                         uint32_t a2, uint32_t a3,
                                         uint32_t b0, uint32_t b1) {
    asm volatile(
        "mma.sync.aligned.m16n8k8.row.col.f32.tf32.tf32.f32 "
        "{%0,%1,%2,%3}, {%4,%5,%6,%7}, {%8,%9}, {%0,%1,%2,%3};\n"
        : "+f"(c[0]), "+f"(c[1]), "+f"(c[2]), "+f"(c[3])
        : "r"(a0), "r"(a1), "r"(a2), "r"(a3), "r"(b0), "r"(b1));
}

// ---------------- residual + LN + FFN + residual (tf32 tensor cores) ----------------
// smem: hs[64][132] tf32, w1s[128][132] tf32, w2s[128][132] tf32, hid[64][132] tf32
#define LDA 132
__global__ void __launch_bounds__(256, 1)
k_final(const float* __restrict__ ent,
        const float* __restrict__ ffg, const float* __restrict__ ffb,
        const float* __restrict__ W1, const float* __restrict__ b1,
        const float* __restrict__ W2, const float* __restrict__ b2,
        float* __restrict__ out) {
    extern __shared__ float sm[];
    float* hs  = sm;                       // 64*132
    float* w1s = hs  + 64 * LDA;           // 128*132
    float* w2s = w1s + 128 * LDA;          // 128*132
    float* hid = w2s + 128 * LDA;          // 64*132
    int tid = threadIdx.x;
    int bm  = blockIdx.x * 64;
    int lane = tid & 31;
    int wid  = tid >> 5;
    int rg = wid & 3;              // row group: rows rg*16 .. rg*16+15
    int cg = wid >> 2;             // col group: cols cg*64 .. cg*64+63
    int g  = lane >> 2;            // 0..7
    int tg = lane & 3;             // 0..3

    // load rst = featA + ent, fp32 into hs
    for (int i = tid; i < 2048; i += 256) {
        int r = bm + (i >> 5);
        float4 v = {0.f, 0.f, 0.f, 0.f};
        if (r < NN) {
            float4 fa = ((const float4*)g_featA)[(size_t)r * 32 + (i & 31)];
            float4 en = ((const float4*)ent)[(size_t)r * 32 + (i & 31)];
            v.x = fa.x + en.x; v.y = fa.y + en.y; v.z = fa.z + en.z; v.w = fa.w + en.w;
        }
        ((float4*)(hs + (i >> 5) * LDA))[i & 31] = v;
    }
    __syncthreads();

    // LayerNorm rows, write back tf32-rounded
    for (int rr = 0; rr < 8; rr++) {
        int r = wid * 8 + rr;
        float v0 = hs[r * LDA + lane],       v1 = hs[r * LDA + lane + 32],
              v2 = hs[r * LDA + lane + 64],  v3 = hs[r * LDA + lane + 96];
        float s = v0 + v1 + v2 + v3;
        float sq = v0*v0 + v1*v1 + v2*v2 + v3*v3;
        for (int o = 16; o; o >>= 1) {
            s  += __shfl_xor_sync(~0u, s, o);
            sq += __shfl_xor_sync(~0u, sq, o);
        }
        float mu = s * (1.f / 128.f);
        float sc = rsqrtf(sq * (1.f / 128.f) - mu * mu + 1e-5f);
        hs[r * LDA + lane]      = __uint_as_float(f2tf((v0 - mu) * sc * ffg[lane]      + ffb[lane]));
        hs[r * LDA + lane + 32] = __uint_as_float(f2tf((v1 - mu) * sc * ffg[lane + 32] + ffb[lane + 32]));
        hs[r * LDA + lane + 64] = __uint_as_float(f2tf((v2 - mu) * sc * ffg[lane + 64] + ffb[lane + 64]));
        hs[r * LDA + lane + 96] = __uint_as_float(f2tf((v3 - mu) * sc * ffg[lane + 96] + ffb[lane + 96]));
    }
    __syncthreads();

    float oacc[8][4];
    #pragma unroll
    for (int nt = 0; nt < 8; nt++) { oacc[nt][0]=oacc[nt][1]=oacc[nt][2]=oacc[nt][3]=0.f; }

    for (int c = 0; c < 4; c++) {
        // load W1 chunk [128 x 128] (cols c*128..) and W2 chunk (rows c*128..), tf32
        for (int i = tid; i < 4096; i += 256) {
            int k = i >> 5, j4 = i & 31;
            float4 v = ((const float4*)(W1 + (size_t)k * 512 + c * 128))[j4];
            float4 o;
            o.x = __uint_as_float(f2tf(v.x)); o.y = __uint_as_float(f2tf(v.y));
            o.z = __uint_as_float(f2tf(v.z)); o.w = __uint_as_float(f2tf(v.w));
            ((float4*)(w1s + k * LDA))[j4] = o;
        }
        for (int i = tid; i < 4096; i += 256) {
            int k = i >> 5, j4 = i & 31;
            float4 v = ((const float4*)(W2 + (size_t)(c * 128 + k) * 128))[j4];
            float4 o;
            o.x = __uint_as_float(f2tf(v.x)); o.y = __uint_as_float(f2tf(v.y));
            o.z = __uint_as_float(f2tf(v.z)); o.w = __uint_as_float(f2tf(v.w));
            ((float4*)(w2s + k * LDA))[j4] = o;
        }
        __syncthreads();

        // Stage 1: Hchunk[64x128] = hs[64x128] @ w1s[128x128]; warp: rows rg*16, cols cg*64 (8 n-tiles)
        float hacc[8][4];
        #pragma unroll
        for (int nt = 0; nt < 8; nt++) { hacc[nt][0]=hacc[nt][1]=hacc[nt][2]=hacc[nt][3]=0.f; }
        for (int ks = 0; ks < 16; ks++) {
            int k0 = ks * 8;
            const float* arow0 = hs + (rg * 16 + g) * LDA + k0;
            const float* arow1 = arow0 + 8 * LDA;
            uint32_t a0 = __float_as_uint(arow0[tg]);
            uint32_t a1 = __float_as_uint(arow1[tg]);
            uint32_t a2 = __float_as_uint(arow0[tg + 4]);
            uint32_t a3 = __float_as_uint(arow1[tg + 4]);
            const float* bb0 = w1s + (k0 + tg) * LDA + cg * 64 + g;
            const float* bb1 = bb0 + 4 * LDA;
            #pragma unroll
            for (int nt = 0; nt < 8; nt++) {
                uint32_t b0 = __float_as_uint(bb0[nt * 8]);
                uint32_t b1 = __float_as_uint(bb1[nt * 8]);
                mma_tf32(hacc[nt], a0, a1, a2, a3, b0, b1);
            }
        }
        // bias + relu + store tf32 to hid
        #pragma unroll
        for (int nt = 0; nt < 8; nt++) {
            int col = cg * 64 + nt * 8 + 2 * tg;
            float bb0 = b1[c * 128 + col], bb1 = b1[c * 128 + col + 1];
            float h0 = fmaxf(hacc[nt][0] + bb0, 0.f);
            float h1 = fmaxf(hacc[nt][1] + bb1, 0.f);
            float h2 = fmaxf(hacc[nt][2] + bb0, 0.f);
            float h3 = fmaxf(hacc[nt][3] + bb1, 0.f);
            hid[(rg * 16 + g)     * LDA + col]     = __uint_as_float(f2tf(h0));
            hid[(rg * 16 + g)     * LDA + col + 1] = __uint_as_float(f2tf(h1));
            hid[(rg * 16 + g + 8) * LDA + col]     = __uint_as_float(f2tf(h2));
            hid[(rg * 16 + g + 8) * LDA + col + 1] = __uint_as_float(f2tf(h3));
        }
        __syncthreads();

        // Stage 2: O += Hchunk[64x128] @ w2s[128x128]; warp: rows rg*16, cols cg*64
        for (int ks = 0; ks < 16; ks++) {
            int k0 = ks * 8;
            const float* arow0 = hid + (rg * 16 + g) * LDA + k0;
            const float* arow1 = arow0 + 8 * LDA;
            uint32_t a0 = __float_as_uint(arow0[tg]);
            uint32_t a1 = __float_as_uint(arow1[tg]);
            uint32_t a2 = __float_as_uint(arow0[tg + 4]);
            uint32_t a3 = __float_as_uint(arow1[tg + 4]);
            const float* bb0 = w2s + (k0 + tg) * LDA + cg * 64 + g;
            const float* bb1 = bb0 + 4 * LDA;
            #pragma unroll
            for (int nt = 0; nt < 8; nt++) {
                uint32_t b0 = __float_as_uint(bb0[nt * 8]);
                uint32_t b1 = __float_as_uint(bb1[nt * 8]);
                mma_tf32(oacc[nt], a0, a1, a2, a3, b0, b1);
            }
        }
        __syncthreads();
    }

    // epilogue: + b2 + featA + ent
    #pragma unroll
    for (int nt = 0; nt < 8; nt++) {
        int col = cg * 64 + nt * 8 + 2 * tg;
        float bb0 = b2[col], bb1 = b2[col + 1];
        int r0c = bm + rg * 16 + g;
        int r1c = r0c + 8;
        if (r0c < NN) {
            float2 fa = *(const float2*)(g_featA + (size_t)r0c * 128 + col);
            float2 en = *(const float2*)(ent     + (size_t)r0c * 128 + col);
            float2 o;
            o.x = oacc[nt][0] + bb0 + fa.x + en.x;
            o.y = oacc[nt][1] + bb1 + fa.y + en.y;
            *(float2*)(out + (size_t)r0c * 128 + col) = o;
        }
        if (r1c < NN) {
            float2 fa = *(const float2*)(g_featA + (size_t)r1c * 128 + col);
            float2 en = *(const float2*)(ent     + (size_t)r1c * 128 + col);
            float2 o;
            o.x = oacc[nt][2] + bb0 + fa.x + en.x;
            o.y = oacc[nt][3] + bb1 + fa.y + en.y;
            *(float2*)(out + (size_t)r1c * 128 + col) = o;
        }
    }
}

// ---------------- launch ----------------
extern "C" void kernel_launch(void* const* d_in, const int* in_sizes, int n_in,
                              void* d_out, int out_size) {
    const float* ent    = (const float*)d_in[0];
    const float* rel    = (const float*)d_in[1];
    const int*   src    = (const int*)  d_in[2];
    const int*   dst    = (const int*)  d_in[3];
    const int*   rid    = (const int*)  d_in[4];
    const float* Wh     = (const float*)d_in[5];
    const float* Wt     = (const float*)d_in[6];
    const float* We     = (const float*)d_in[7];
    const float* Wr     = (const float*)d_in[8];
    const float* attn_r = (const float*)d_in[9];
    const float* lng    = (const float*)d_in[10];
    const float* lnb    = (const float*)d_in[11];
    const float* lrg    = (const float*)d_in[12];
    const float* lrb    = (const float*)d_in[13];
    const float* ffg    = (const float*)d_in[14];
    const float* ffb    = (const float*)d_in[15];
    const float* W1     = (const float*)d_in[16];
    const float* b1     = (const float*)d_in[17];
    const float* W2     = (const float*)d_in[18];
    const float* b2     = (const float*)d_in[19];
    float* out = (float*)d_out;

    const int final_smem = (64 * LDA + 128 * LDA + 128 * LDA + 64 * LDA) * 4;  // 202752 B
    cudaFuncSetAttribute(k_proj,  cudaFuncAttributeMaxDynamicSharedMemorySize, 96 * 1024);
    cudaFuncSetAttribute(k_final, cudaFuncAttributeMaxDynamicSharedMemorySize, final_smem);

    k_zero_deg<<<(NN + 255) / 256, 256>>>();
    k_hist<<<(EE + 255) / 256, 256>>>(dst);
    k_scan<<<1, 1024>>>();
    k_scatter<<<(EE + 255) / 256, 256>>>(dst, src, rid);
    k_rel<<<1, 256>>>(rel, Wr, attn_r, lrg, lrb);
    k_proj<<<(NN + 63) / 64, 256, 96 * 1024>>>(ent, Wh, Wt, We, lng, lnb);
    k_scores<<<(NN + 7) / 8, 256>>>();
    for (int it = 0; it < 5; it++)
        k_diff<<<(NN + 7) / 8, 256>>>(it);
    k_final<<<(NN + 63) / 64, 256, final_smem>>>(ent, ffg, ffb, W1, b1, W2, b2, out);
}

// round 4
// speedup vs baseline: 1.6000x; 1.1838x over previous
#include <cuda_runtime.h>
#include <cuda_bf16.h>
#include <math.h>
#include <stdint.h>

#define NN   50000
#define EE   800000
#define RRR  32
#define DIN  128
#define HHH  8
#define DDD  16
#define HD   128

// ---------------- device scratch ----------------
__device__ float g_fhead[NN * HD];
__device__ float g_ftail[NN * HD];
__device__ float g_fent [NN * HD];
__device__ float g_featA[NN * HD];
__device__ float g_featB[NN * HD];
__device__ float g_attn [EE * HHH];      // CSR-position-ordered attention
__device__ float g_er   [RRR * HHH];
__device__ float g_login[NN];
__device__ int   g_deg   [NN];
__device__ int   g_rowptr[NN + 1];
__device__ int   g_cursor[NN];
__device__ int   g_esrc  [EE];           // src node id, CSR order
__device__ int   g_erid  [EE];           // relation id, CSR order

// ---------------- CSR build ----------------
__global__ void k_zero_deg() {
    int i = blockIdx.x * blockDim.x + threadIdx.x;
    if (i < NN) g_deg[i] = 0;
}

__global__ void k_hist(const int* __restrict__ dst) {
    int e = blockIdx.x * blockDim.x + threadIdx.x;
    if (e < EE) atomicAdd(&g_deg[dst[e]], 1);
}

__global__ void k_scan() {   // 1 block, 1024 threads
    __shared__ int sums[1024];
    int tid = threadIdx.x;
    const int C = (NN + 1023) / 1024;
    int start = tid * C;
    int end   = min(start + C, NN);
    int s = 0;
    for (int i = start; i < end; i++) s += g_deg[i];
    sums[tid] = s;
    __syncthreads();
    for (int off = 1; off < 1024; off <<= 1) {
        int v = (tid >= off) ? sums[tid - off] : 0;
        __syncthreads();
        sums[tid] += v;
        __syncthreads();
    }
    int base = (tid == 0) ? 0 : sums[tid - 1];
    for (int i = start; i < end; i++) {
        g_rowptr[i] = base;
        int d = g_deg[i];
        g_login[i] = logf((float)max(d, 1)) * 0.25f;   // /sqrt(16)
        g_cursor[i] = 0;
        base += d;
    }
    if (tid == 1023) g_rowptr[NN] = sums[1023];
}

__global__ void k_scatter(const int* __restrict__ dst, const int* __restrict__ src,
                          const int* __restrict__ rid) {
    int e = blockIdx.x * blockDim.x + threadIdx.x;
    if (e < EE) {
        int d = dst[e];
        int p = atomicAdd(&g_cursor[d], 1);
        int pos = g_rowptr[d] + p;
        g_esrc[pos] = src[e];
        g_erid[pos] = rid[e];
    }
}

// ---------------- relation branch ----------------
__global__ void k_rel(const float* __restrict__ rel_feat, const float* __restrict__ W_rel,
                      const float* __restrict__ attn_r,
                      const float* __restrict__ lng, const float* __restrict__ lnb) {
    __shared__ float rn[RRR * DIN];
    __shared__ float frel[RRR * HD];
    int tid = threadIdx.x;
    for (int i = tid; i < RRR * DIN; i += 256) rn[i] = rel_feat[i];
    __syncthreads();
    int w = tid >> 5, lane = tid & 31;
    for (int rr = 0; rr < 4; rr++) {
        int r = w * 4 + rr;
        float s = 0.f, sq = 0.f;
        for (int j = lane; j < DIN; j += 32) { float v = rn[r * DIN + j]; s += v; sq += v * v; }
        for (int o = 16; o; o >>= 1) {
            s  += __shfl_xor_sync(~0u, s, o);
            sq += __shfl_xor_sync(~0u, sq, o);
        }
        float m  = s / DIN;
        float sc = rsqrtf(sq / DIN - m * m + 1e-5f);
        for (int j = lane; j < DIN; j += 32)
            rn[r * DIN + j] = (rn[r * DIN + j] - m) * sc * lng[j] + lnb[j];
    }
    __syncthreads();
    for (int i = tid; i < RRR * HD; i += 256) {
        int r = i / HD, j = i % HD;
        float acc = 0.f;
        for (int k = 0; k < DIN; k++) acc += rn[r * DIN + k] * W_rel[k * HD + j];
        frel[i] = acc;
    }
    __syncthreads();
    if (tid < RRR * HHH) {
        int r = tid / HHH, h = tid % HHH;
        float acc = 0.f;
        for (int d = 0; d < DDD; d++) acc += frel[r * HD + h * DDD + d] * attn_r[h * DDD + d];
        g_er[tid] = acc;
    }
}

// ---------------- LN(ent) + 3 projections (fp32, M-tile 64) ----------------
__global__ void k_proj(const float* __restrict__ ent,
                       const float* __restrict__ Wh, const float* __restrict__ Wt,
                       const float* __restrict__ We,
                       const float* __restrict__ lng, const float* __restrict__ lnb) {
    extern __shared__ float sm[];
    float* xs = sm;                // 64*128
    float* ws = sm + 64 * 128;     // 128*128
    int tid = threadIdx.x;
    int bm  = blockIdx.x * 64;

    for (int i = tid; i < 2048; i += 256) {
        int r = bm + (i >> 5);
        float4 v = {0.f, 0.f, 0.f, 0.f};
        if (r < NN) v = ((const float4*)ent)[r * 32 + (i & 31)];
        ((float4*)xs)[i] = v;
    }
    __syncthreads();

    int w = tid >> 5, lane = tid & 31;
    for (int rr = 0; rr < 8; rr++) {
        int r = w * 8 + rr;
        float v0 = xs[r * 128 + lane], v1 = xs[r * 128 + lane + 32],
              v2 = xs[r * 128 + lane + 64], v3 = xs[r * 128 + lane + 96];
        float s = v0 + v1 + v2 + v3;
        float sq = v0 * v0 + v1 * v1 + v2 * v2 + v3 * v3;
        for (int o = 16; o; o >>= 1) {
            s  += __shfl_xor_sync(~0u, s, o);
            sq += __shfl_xor_sync(~0u, sq, o);
        }
        float m  = s * (1.f / 128.f);
        float sc = rsqrtf(sq * (1.f / 128.f) - m * m + 1e-5f);
        xs[r * 128 + lane]      = (v0 - m) * sc * lng[lane]      + lnb[lane];
        xs[r * 128 + lane + 32] = (v1 - m) * sc * lng[lane + 32] + lnb[lane + 32];
        xs[r * 128 + lane + 64] = (v2 - m) * sc * lng[lane + 64] + lnb[lane + 64];
        xs[r * 128 + lane + 96] = (v3 - m) * sc * lng[lane + 96] + lnb[lane + 96];
    }
    __syncthreads();

    int tx = tid & 31, ty = tid >> 5;
    const float* Ws[3] = {Wh, Wt, We};
    float* Os[3] = {g_fhead, g_ftail, g_fent};
    for (int wi = 0; wi < 3; wi++) {
        for (int i = tid; i < 4096; i += 256)
            ((float4*)ws)[i] = ((const float4*)Ws[wi])[i];
        __syncthreads();
        float acc[8][4];
        #pragma unroll
        for (int im = 0; im < 8; im++) { acc[im][0]=acc[im][1]=acc[im][2]=acc[im][3]=0.f; }
        for (int k = 0; k < 128; k++) {
            float4 bv = ((float4*)(ws + k * 128))[tx];
            #pragma unroll
            for (int im = 0; im < 8; im++) {
                float av = xs[(ty * 8 + im) * 128 + k];
                acc[im][0] += av * bv.x; acc[im][1] += av * bv.y;
                acc[im][2] += av * bv.z; acc[im][3] += av * bv.w;
            }
        }
        #pragma unroll
        for (int im = 0; im < 8; im++) {
            int r = bm + ty * 8 + im;
            if (r < NN) {
                float4 o = {acc[im][0], acc[im][1], acc[im][2], acc[im][3]};
                ((float4*)(Os[wi] + r * 128))[tx] = o;
            }
        }
        __syncthreads();
    }
}

// ---------------- edge scores + segment softmax (no-max: logits are tiny) ----------------
__global__ void k_scores() {
    int warp = (blockIdx.x * blockDim.x + threadIdx.x) >> 5;
    if (warp >= NN) return;
    int lane = threadIdx.x & 31;
    int h = lane >> 2, kk = lane & 3;
    int d = warp;
    float4 t = ((const float4*)(g_ftail + d * 128))[lane];
    int r0 = g_rowptr[d], r1 = g_rowptr[d + 1];
    float login = g_login[d];
    float s = 0.f;

    int i = r0;
    for (; i + 4 <= r1; i += 4) {
        int sn0 = g_esrc[i],   sn1 = g_esrc[i+1], sn2 = g_esrc[i+2], sn3 = g_esrc[i+3];
        int rv0 = g_erid[i],   rv1 = g_erid[i+1], rv2 = g_erid[i+2], rv3 = g_erid[i+3];
        float4 h0 = ((const float4*)(g_fhead + (size_t)sn0 * 128))[lane];
        float4 h1 = ((const float4*)(g_fhead + (size_t)sn1 * 128))[lane];
        float4 h2 = ((const float4*)(g_fhead + (size_t)sn2 * 128))[lane];
        float4 h3 = ((const float4*)(g_fhead + (size_t)sn3 * 128))[lane];
        float p0 = h0.x*t.x + h0.y*t.y + h0.z*t.z + h0.w*t.w;
        float p1 = h1.x*t.x + h1.y*t.y + h1.z*t.z + h1.w*t.w;
        float p2 = h2.x*t.x + h2.y*t.y + h2.z*t.z + h2.w*t.w;
        float p3 = h3.x*t.x + h3.y*t.y + h3.z*t.z + h3.w*t.w;
        p0 += __shfl_xor_sync(~0u, p0, 1); p0 += __shfl_xor_sync(~0u, p0, 2);
        p1 += __shfl_xor_sync(~0u, p1, 1); p1 += __shfl_xor_sync(~0u, p1, 2);
        p2 += __shfl_xor_sync(~0u, p2, 1); p2 += __shfl_xor_sync(~0u, p2, 2);
        p3 += __shfl_xor_sync(~0u, p3, 1); p3 += __shfl_xor_sync(~0u, p3, 2);
        float x0 = __expf(p0 * g_er[rv0 * 8 + h] * login);
        float x1 = __expf(p1 * g_er[rv1 * 8 + h] * login);
        float x2 = __expf(p2 * g_er[rv2 * 8 + h] * login);
        float x3 = __expf(p3 * g_er[rv3 * 8 + h] * login);
        if (kk == 0) {
            g_attn[(size_t)(i  ) * 8 + h] = x0;
            g_attn[(size_t)(i+1) * 8 + h] = x1;
            g_attn[(size_t)(i+2) * 8 + h] = x2;
            g_attn[(size_t)(i+3) * 8 + h] = x3;
        }
        s += (x0 + x1) + (x2 + x3);
    }
    for (; i < r1; i++) {
        int sn = g_esrc[i];
        int rv = g_erid[i];
        float4 hh = ((const float4*)(g_fhead + (size_t)sn * 128))[lane];
        float p = hh.x*t.x + hh.y*t.y + hh.z*t.z + hh.w*t.w;
        p += __shfl_xor_sync(~0u, p, 1);
        p += __shfl_xor_sync(~0u, p, 2);
        float x = __expf(p * g_er[rv * 8 + h] * login);
        if (kk == 0) g_attn[(size_t)i * 8 + h] = x;
        s += x;
    }
    float inv = 1.f / s;
    // all 32 lanes scale: lane (h, kk) handles edges j = r0+kk, r0+kk+4, ... -> coalesced
    for (int j = r0 + kk; j < r1; j += 4)
        g_attn[(size_t)j * 8 + h] *= inv;
}

// ---------------- one PPR diffusion hop (warp per dst, unroll-8) ----------------
__global__ void k_diff(int iter) {
    const float* fin;
    float* fout;
    if (iter == 0)      { fin = g_fent;  fout = g_featA; }
    else if (iter & 1)  { fin = g_featA; fout = g_featB; }
    else                { fin = g_featB; fout = g_featA; }
    int warp = (blockIdx.x * blockDim.x + threadIdx.x) >> 5;
    if (warp >= NN) return;
    int lane = threadIdx.x & 31;
    int d = warp;
    int r0 = g_rowptr[d], r1 = g_rowptr[d + 1];
    int hsel = lane >> 2;
    float4 acc = {0.f, 0.f, 0.f, 0.f};

    int i = r0;
    for (; i + 8 <= r1; i += 8) {
        int sn0 = g_esrc[i],   sn1 = g_esrc[i+1], sn2 = g_esrc[i+2], sn3 = g_esrc[i+3];
        int sn4 = g_esrc[i+4], sn5 = g_esrc[i+5], sn6 = g_esrc[i+6], sn7 = g_esrc[i+7];
        float a0 = g_attn[(size_t)(i  ) * 8 + hsel];
        float a1 = g_attn[(size_t)(i+1) * 8 + hsel];
        float a2 = g_attn[(size_t)(i+2) * 8 + hsel];
        float a3 = g_attn[(size_t)(i+3) * 8 + hsel];
        float a4 = g_attn[(size_t)(i+4) * 8 + hsel];
        float a5 = g_attn[(size_t)(i+5) * 8 + hsel];
        float a6 = g_attn[(size_t)(i+6) * 8 + hsel];
        float a7 = g_attn[(size_t)(i+7) * 8 + hsel];
        float4 f0 = ((const float4*)(fin + (size_t)sn0 * 128))[lane];
        float4 f1 = ((const float4*)(fin + (size_t)sn1 * 128))[lane];
        float4 f2 = ((const float4*)(fin + (size_t)sn2 * 128))[lane];
        float4 f3 = ((const float4*)(fin + (size_t)sn3 * 128))[lane];
        float4 f4 = ((const float4*)(fin + (size_t)sn4 * 128))[lane];
        float4 f5 = ((const float4*)(fin + (size_t)sn5 * 128))[lane];
        float4 f6 = ((const float4*)(fin + (size_t)sn6 * 128))[lane];
        float4 f7 = ((const float4*)(fin + (size_t)sn7 * 128))[lane];
        acc.x += f0.x*a0 + f1.x*a1 + f2.x*a2 + f3.x*a3 + f4.x*a4 + f5.x*a5 + f6.x*a6 + f7.x*a7;
        acc.y += f0.y*a0 + f1.y*a1 + f2.y*a2 + f3.y*a3 + f4.y*a4 + f5.y*a5 + f6.y*a6 + f7.y*a7;
        acc.z += f0.z*a0 + f1.z*a1 + f2.z*a2 + f3.z*a3 + f4.z*a4 + f5.z*a5 + f6.z*a6 + f7.z*a7;
        acc.w += f0.w*a0 + f1.w*a1 + f2.w*a2 + f3.w*a3 + f4.w*a4 + f5.w*a5 + f6.w*a6 + f7.w*a7;
    }
    for (; i < r1; i++) {
        int sn = g_esrc[i];
        float a = g_attn[(size_t)i * 8 + hsel];
        float4 f = ((const float4*)(fin + (size_t)sn * 128))[lane];
        acc.x += f.x * a; acc.y += f.y * a; acc.z += f.z * a; acc.w += f.w * a;
    }
    float4 fe = ((const float4*)(g_fent + d * 128))[lane];
    float4 o;
    o.x = 0.9f * acc.x + 0.1f * fe.x;
    o.y = 0.9f * acc.y + 0.1f * fe.y;
    o.z = 0.9f * acc.z + 0.1f * fe.z;
    o.w = 0.9f * acc.w + 0.1f * fe.w;
    ((float4*)(fout + d * 128))[lane] = o;
}

// ---------------- bf16 mma helpers ----------------
__device__ __forceinline__ void ldsm_x4(uint32_t& r0, uint32_t& r1, uint32_t& r2, uint32_t& r3,
                                        uint32_t addr) {
    asm volatile("ldmatrix.sync.aligned.m8n8.x4.shared.b16 {%0,%1,%2,%3}, [%4];"
                 : "=r"(r0), "=r"(r1), "=r"(r2), "=r"(r3) : "r"(addr));
}
__device__ __forceinline__ void ldsm_x2t(uint32_t& r0, uint32_t& r1, uint32_t addr) {
    asm volatile("ldmatrix.sync.aligned.m8n8.x2.trans.shared.b16 {%0,%1}, [%2];"
                 : "=r"(r0), "=r"(r1) : "r"(addr));
}
__device__ __forceinline__ void mma_bf16(float c[4], uint32_t a0, uint32_t a1,
                                         uint32_t a2, uint32_t a3,
                                         uint32_t b0, uint32_t b1) {
    asm volatile(
        "mma.sync.aligned.m16n8k16.row.col.f32.bf16.bf16.f32 "
        "{%0,%1,%2,%3}, {%4,%5,%6,%7}, {%8,%9}, {%0,%1,%2,%3};\n"
        : "+f"(c[0]), "+f"(c[1]), "+f"(c[2]), "+f"(c[3])
        : "r"(a0), "r"(a1), "r"(a2), "r"(a3), "r"(b0), "r"(b1));
}

// ---------------- residual + LN + FFN + residual (bf16 mma, M-tile 128) ----------------
// smem bf16 arrays, LDB = 136 elems (272 B rows -> conflict-free ldmatrix)
#define LDB 136
#define MT  128
__global__ void __launch_bounds__(256, 1)
k_final(const float* __restrict__ ent,
        const float* __restrict__ ffg, const float* __restrict__ ffb,
        const float* __restrict__ W1, const float* __restrict__ b1,
        const float* __restrict__ W2, const float* __restrict__ b2,
        float* __restrict__ out) {
    extern __shared__ char smc[];
    __nv_bfloat16* hs  = (__nv_bfloat16*)smc;                       // 128*136
    __nv_bfloat16* w1s = hs  + MT * LDB;                            // 128*136
    __nv_bfloat16* w2s = w1s + 128 * LDB;                           // 128*136
    __nv_bfloat16* hid = w2s + 128 * LDB;                           // 128*136
    float* stage = (float*)w1s;    // fp32 staging [128][136], exactly spans w1s+w2s

    int tid = threadIdx.x;
    int bm  = blockIdx.x * MT;
    int lane = tid & 31;
    int wid  = tid >> 5;
    int g  = lane >> 2;            // 0..7
    int tg = lane & 3;             // 0..3
    int m0 = wid * 16;             // warp's 16 rows

    // phase A: rst = featA + ent (fp32) into stage
    for (int i = tid; i < MT * 32; i += 256) {
        int ri = i >> 5, c4 = i & 31;
        int r = bm + ri;
        float4 v = {0.f, 0.f, 0.f, 0.f};
        if (r < NN) {
            float4 fa = ((const float4*)g_featA)[(size_t)r * 32 + c4];
            float4 en = ((const float4*)ent)[(size_t)r * 32 + c4];
            v.x = fa.x + en.x; v.y = fa.y + en.y; v.z = fa.z + en.z; v.w = fa.w + en.w;
        }
        *(float4*)(stage + ri * LDB + c4 * 4) = v;
    }
    __syncthreads();

    // LayerNorm -> bf16 hs
    for (int rr = 0; rr < 16; rr++) {
        int r = wid * 16 + rr;
        const float* row = stage + r * LDB;
        float v0 = row[lane], v1 = row[lane + 32], v2 = row[lane + 64], v3 = row[lane + 96];
        float s = v0 + v1 + v2 + v3;
        float sq = v0*v0 + v1*v1 + v2*v2 + v3*v3;
        for (int o = 16; o; o >>= 1) {
            s  += __shfl_xor_sync(~0u, s, o);
            sq += __shfl_xor_sync(~0u, sq, o);
        }
        float mu = s * (1.f / 128.f);
        float sc = rsqrtf(sq * (1.f / 128.f) - mu * mu + 1e-5f);
        int c0 = 2 * lane, c1 = 2 * lane + 64;
        float p0 = (row[c0]     - mu) * sc * ffg[c0]     + ffb[c0];
        float p1 = (row[c0 + 1] - mu) * sc * ffg[c0 + 1] + ffb[c0 + 1];
        float p2 = (row[c1]     - mu) * sc * ffg[c1]     + ffb[c1];
        float p3 = (row[c1 + 1] - mu) * sc * ffg[c1 + 1] + ffb[c1 + 1];
        *(__nv_bfloat162*)(hs + r * LDB + c0) = __floats2bfloat162_rn(p0, p1);
        *(__nv_bfloat162*)(hs + r * LDB + c1) = __floats2bfloat162_rn(p2, p3);
    }
    __syncthreads();

    uint32_t hs_s  = (uint32_t)__cvta_generic_to_shared(hs);
    uint32_t w1_s  = (uint32_t)__cvta_generic_to_shared(w1s);
    uint32_t w2_s  = (uint32_t)__cvta_generic_to_shared(w2s);
    uint32_t hid_s = (uint32_t)__cvta_generic_to_shared(hid);
    int arow = m0 + (lane & 15);
    int acoff = (lane >> 4) << 3;
    uint32_t aA_base = hs_s  + (uint32_t)(arow * LDB + acoff) * 2;
    uint32_t aH_base = hid_s + (uint32_t)(arow * LDB + acoff) * 2;
    uint32_t b1_base = w1_s + (uint32_t)((lane & 15) * LDB) * 2;
    uint32_t b2_base = w2_s + (uint32_t)((lane & 15) * LDB) * 2;

    float oacc[16][4];
    #pragma unroll
    for (int nt = 0; nt < 16; nt++) { oacc[nt][0]=oacc[nt][1]=oacc[nt][2]=oacc[nt][3]=0.f; }

    for (int c = 0; c < 4; c++) {
        // load W1 chunk [k=128][n=c*128..+128] and W2 chunk [k=c*128..+128][n=128], bf16
        for (int i = tid; i < 4096; i += 256) {
            int k = i >> 5, j4 = i & 31;
            float4 v = *(const float4*)(W1 + (size_t)k * 512 + c * 128 + 4 * j4);
            __nv_bfloat162 lo = __floats2bfloat162_rn(v.x, v.y);
            __nv_bfloat162 hi = __floats2bfloat162_rn(v.z, v.w);
            uint2 pk = make_uint2(*(uint32_t*)&lo, *(uint32_t*)&hi);
            *(uint2*)(w1s + k * LDB + 4 * j4) = pk;
        }
        for (int i = tid; i < 4096; i += 256) {
            int k = i >> 5, j4 = i & 31;
            float4 v = *(const float4*)(W2 + (size_t)(c * 128 + k) * 128 + 4 * j4);
            __nv_bfloat162 lo = __floats2bfloat162_rn(v.x, v.y);
            __nv_bfloat162 hi = __floats2bfloat162_rn(v.z, v.w);
            uint2 pk = make_uint2(*(uint32_t*)&lo, *(uint32_t*)&hi);
            *(uint2*)(w2s + k * LDB + 4 * j4) = pk;
        }
        __syncthreads();

        // stage 1: Hc[128x128] = hs @ W1c ; warp: rows m0..m0+15, all 128 cols (16 n-tiles)
        float hacc[16][4];
        #pragma unroll
        for (int nt = 0; nt < 16; nt++) { hacc[nt][0]=hacc[nt][1]=hacc[nt][2]=hacc[nt][3]=0.f; }
        #pragma unroll
        for (int ks = 0; ks < 8; ks++) {
            uint32_t a0, a1, a2, a3;
            ldsm_x4(a0, a1, a2, a3, aA_base + ks * 32);
            uint32_t bk = b1_base + ks * 16 * LDB * 2;
            #pragma unroll
            for (int nt = 0; nt < 16; nt++) {
                uint32_t b0, b1r;
                ldsm_x2t(b0, b1r, bk + nt * 16);
                mma_bf16(hacc[nt], a0, a1, a2, a3, b0, b1r);
            }
        }
        // bias + relu -> hid (bf16)
        #pragma unroll
        for (int nt = 0; nt < 16; nt++) {
            int col = nt * 8 + 2 * tg;
            float bb0 = b1[c * 128 + col], bb1 = b1[c * 128 + col + 1];
            float h0 = fmaxf(hacc[nt][0] + bb0, 0.f);
            float h1 = fmaxf(hacc[nt][1] + bb1, 0.f);
            float h2 = fmaxf(hacc[nt][2] + bb0, 0.f);
            float h3 = fmaxf(hacc[nt][3] + bb1, 0.f);
            *(__nv_bfloat162*)(hid + (m0 + g)     * LDB + col) = __floats2bfloat162_rn(h0, h1);
            *(__nv_bfloat162*)(hid + (m0 + g + 8) * LDB + col) = __floats2bfloat162_rn(h2, h3);
        }
        __syncwarp();   // warp reads back only its own hid rows

        // stage 2: O += Hc @ W2c
        #pragma unroll
        for (int ks = 0; ks < 8; ks++) {
            uint32_t a0, a1, a2, a3;
            ldsm_x4(a0, a1, a2, a3, aH_base + ks * 32);
            uint32_t bk = b2_base + ks * 16 * LDB * 2;
            #pragma unroll
            for (int nt = 0; nt < 16; nt++) {
                uint32_t b0, b1r;
                ldsm_x2t(b0, b1r, bk + nt * 16);
                mma_bf16(oacc[nt], a0, a1, a2, a3, b0, b1r);
            }
        }
        __syncthreads();   // before next chunk overwrites w1s/w2s
    }

    // epilogue: + b2 + featA + ent
    #pragma unroll
    for (int nt = 0; nt < 16; nt++) {
        int col = nt * 8 + 2 * tg;
        float bb0 = b2[col], bb1 = b2[col + 1];
        int r0c = bm + m0 + g;
        int r1c = r0c + 8;
        if (r0c < NN) {
            float2 fa = *(const float2*)(g_featA + (size_t)r0c * 128 + col);
            float2 en = *(const float2*)(ent     + (size_t)r0c * 128 + col);
            float2 o;
            o.x = oacc[nt][0] + bb0 + fa.x + en.x;
            o.y = oacc[nt][1] + bb1 + fa.y + en.y;
            *(float2*)(out + (size_t)r0c * 128 + col) = o;
        }
        if (r1c < NN) {
            float2 fa = *(const float2*)(g_featA + (size_t)r1c * 128 + col);
            float2 en = *(const float2*)(ent     + (size_t)r1c * 128 + col);
            float2 o;
            o.x = oacc[nt][2] + bb0 + fa.x + en.x;
            o.y = oacc[nt][3] + bb1 + fa.y + en.y;
            *(float2*)(out + (size_t)r1c * 128 + col) = o;
        }
    }
}

// ---------------- launch ----------------
extern "C" void kernel_launch(void* const* d_in, const int* in_sizes, int n_in,
                              void* d_out, int out_size) {
    const float* ent    = (const float*)d_in[0];
    const float* rel    = (const float*)d_in[1];
    const int*   src    = (const int*)  d_in[2];
    const int*   dst    = (const int*)  d_in[3];
    const int*   rid    = (const int*)  d_in[4];
    const float* Wh     = (const float*)d_in[5];
    const float* Wt     = (const float*)d_in[6];
    const float* We     = (const float*)d_in[7];
    const float* Wr     = (const float*)d_in[8];
    const float* attn_r = (const float*)d_in[9];
    const float* lng    = (const float*)d_in[10];
    const float* lnb    = (const float*)d_in[11];
    const float* lrg    = (const float*)d_in[12];
    const float* lrb    = (const float*)d_in[13];
    const float* ffg    = (const float*)d_in[14];
    const float* ffb    = (const float*)d_in[15];
    const float* W1     = (const float*)d_in[16];
    const float* b1     = (const float*)d_in[17];
    const float* W2     = (const float*)d_in[18];
    const float* b2     = (const float*)d_in[19];
    float* out = (float*)d_out;

    const int final_smem = (MT + 128 + 128 + 128) * LDB * 2;  // 139264 B
    cudaFuncSetAttribute(k_proj,  cudaFuncAttributeMaxDynamicSharedMemorySize, 96 * 1024);
    cudaFuncSetAttribute(k_final, cudaFuncAttributeMaxDynamicSharedMemorySize, final_smem);

    k_zero_deg<<<(NN + 255) / 256, 256>>>();
    k_hist<<<(EE + 255) / 256, 256>>>(dst);
    k_scan<<<1, 1024>>>();
    k_scatter<<<(EE + 255) / 256, 256>>>(dst, src, rid);
    k_rel<<<1, 256>>>(rel, Wr, attn_r, lrg, lrb);
    k_proj<<<(NN + 63) / 64, 256, 96 * 1024>>>(ent, Wh, Wt, We, lng, lnb);
    k_scores<<<(NN + 7) / 8, 256>>>();
    for (int it = 0; it < 5; it++)
        k_diff<<<(NN + 7) / 8, 256>>>(it);
    k_final<<<(NN + MT - 1) / MT, 256, final_smem>>>(ent, ffg, ffb, W1, b1, W2, b2, out);
}